// round 1
// baseline (speedup 1.0000x reference)
#include <cuda_runtime.h>
#include <math.h>

#define B_DIM 16384
#define S_DIM 64
#define A_DIM 16
#define H_DIM 256
#define E_DIM 8
#define K_CAT 2048   // E * H

// Fused hidden activations Hcat[b][e*H + h]  (134 MB scratch)
__device__ float g_H[(size_t)B_DIM * K_CAT];

__device__ __forceinline__ void cp16(float* dst, const float* src) {
    unsigned d = (unsigned)__cvta_generic_to_shared(dst);
    asm volatile("cp.async.cg.shared.global [%0], [%1], 16;" :: "r"(d), "l"(src));
}
__device__ __forceinline__ void cp_commit() { asm volatile("cp.async.commit_group;"); }
template<int N> __device__ __forceinline__ void cp_wait() {
    asm volatile("cp.async.wait_group %0;" :: "n"(N));
}

// ---------------------------------------------------------------------------
// Pass 1: per (64-row batch tile, ensemble member e):
//   h1 = tanh(state @ W1_e + b1_e)   [64,256]
//   h2 = tanh(h1   @ W2_e + b2_e)    [64,256]  -> g_H[b][e*256 + h]
// Thread map: 256 threads, ty=tid/32 (0..7), tx=tid%32.
// Each thread: 8 rows (r = i*8+ty) x 8 cols (tx*4..+3 and 128+tx*4..+3).
// A-operand smem reads are warp-uniform (all lanes share ty) => broadcast.
// B-operand float4 reads are phase-conflict-free (lane stride = 16B).
// ---------------------------------------------------------------------------
__global__ void __launch_bounds__(256, 1) k_fused12(
    const float* __restrict__ state, const float* __restrict__ W1,
    const float* __restrict__ b1,    const float* __restrict__ W2,
    const float* __restrict__ b2)
{
    extern __shared__ float sm[];
    float* sS  = sm;            // phase1: state tile [64][64]
    float* sW1 = sm + 4096;     // phase1: W1_e [64][256]
    float* sH1 = sm + 32768;    // h1 [64][256]
    float* wb0 = sm;            // phase2: W2 chunk buf0 [64][256] (reuses sS/sW1)
    float* wb1 = sm + 16384;    // phase2: W2 chunk buf1 [64][256]

    const int tid = threadIdx.x;
    const int tx = tid & 31, ty = tid >> 5;
    const int b0 = blockIdx.x * 64;
    const int e  = blockIdx.y;
    const int c0 = tx * 4;

    // --- load state tile + full W1_e ---
    #pragma unroll
    for (int j = 0; j < 4; ++j) {
        int lin = j * 256 + tid, row = lin >> 4, seg = lin & 15;
        cp16(sS + row * 64 + seg * 4, state + (size_t)(b0 + row) * S_DIM + seg * 4);
    }
    const float* W1e = W1 + (size_t)e * S_DIM * H_DIM;
    #pragma unroll
    for (int j = 0; j < 16; ++j) {
        int lin = j * 256 + tid, row = lin >> 6, seg = lin & 63;
        cp16(sW1 + row * 256 + seg * 4, W1e + row * 256 + seg * 4);
    }
    cp_commit(); cp_wait<0>(); __syncthreads();

    float acc[8][8];
    #pragma unroll
    for (int i = 0; i < 8; ++i)
        #pragma unroll
        for (int j = 0; j < 8; ++j) acc[i][j] = 0.f;

    // --- layer 1: K = 64 ---
    #pragma unroll 8
    for (int k = 0; k < 64; ++k) {
        float4 v0 = *(const float4*)(sW1 + k * 256 + c0);
        float4 v1 = *(const float4*)(sW1 + k * 256 + 128 + c0);
        #pragma unroll
        for (int i = 0; i < 8; ++i) {
            float a = sS[(i * 8 + ty) * 64 + k];
            acc[i][0] += a * v0.x; acc[i][1] += a * v0.y;
            acc[i][2] += a * v0.z; acc[i][3] += a * v0.w;
            acc[i][4] += a * v1.x; acc[i][5] += a * v1.y;
            acc[i][6] += a * v1.z; acc[i][7] += a * v1.w;
        }
    }
    __syncthreads();   // everyone done reading sS/sW1 (phase2 will overwrite)

    {   // bias + tanh -> sH1
        float4 bb0 = *(const float4*)(b1 + (size_t)e * H_DIM + c0);
        float4 bb1 = *(const float4*)(b1 + (size_t)e * H_DIM + 128 + c0);
        #pragma unroll
        for (int i = 0; i < 8; ++i) {
            int r = i * 8 + ty;
            float4 t0, t1;
            t0.x = tanhf(acc[i][0] + bb0.x); t0.y = tanhf(acc[i][1] + bb0.y);
            t0.z = tanhf(acc[i][2] + bb0.z); t0.w = tanhf(acc[i][3] + bb0.w);
            t1.x = tanhf(acc[i][4] + bb1.x); t1.y = tanhf(acc[i][5] + bb1.y);
            t1.z = tanhf(acc[i][6] + bb1.z); t1.w = tanhf(acc[i][7] + bb1.w);
            *(float4*)(sH1 + r * 256 + c0)       = t0;
            *(float4*)(sH1 + r * 256 + 128 + c0) = t1;
        }
    }
    __syncthreads();

    // --- layer 2: K = 256, streamed in 4 double-buffered chunks of 64 ---
    const float* W2e = W2 + (size_t)e * H_DIM * H_DIM;
    #pragma unroll
    for (int j = 0; j < 16; ++j) {
        int lin = j * 256 + tid, row = lin >> 6, seg = lin & 63;
        cp16(wb0 + row * 256 + seg * 4, W2e + row * 256 + seg * 4);
    }
    cp_commit();

    #pragma unroll
    for (int i = 0; i < 8; ++i)
        #pragma unroll
        for (int j = 0; j < 8; ++j) acc[i][j] = 0.f;

    for (int kc = 0; kc < 4; ++kc) {
        if (kc < 3) {
            float* nb = ((kc + 1) & 1) ? wb1 : wb0;
            const float* src = W2e + (size_t)(kc + 1) * 64 * 256;
            #pragma unroll
            for (int j = 0; j < 16; ++j) {
                int lin = j * 256 + tid, row = lin >> 6, seg = lin & 63;
                cp16(nb + row * 256 + seg * 4, src + row * 256 + seg * 4);
            }
            cp_commit(); cp_wait<1>();
        } else {
            cp_wait<0>();
        }
        __syncthreads();
        const float* sW2 = (kc & 1) ? wb1 : wb0;
        const int kbase = kc * 64;
        #pragma unroll 8
        for (int kk = 0; kk < 64; ++kk) {
            float4 v0 = *(const float4*)(sW2 + kk * 256 + c0);
            float4 v1 = *(const float4*)(sW2 + kk * 256 + 128 + c0);
            #pragma unroll
            for (int i = 0; i < 8; ++i) {
                float a = sH1[(i * 8 + ty) * 256 + kbase + kk];
                acc[i][0] += a * v0.x; acc[i][1] += a * v0.y;
                acc[i][2] += a * v0.z; acc[i][3] += a * v0.w;
                acc[i][4] += a * v1.x; acc[i][5] += a * v1.y;
                acc[i][6] += a * v1.z; acc[i][7] += a * v1.w;
            }
        }
        __syncthreads();
    }

    // bias + tanh -> Hcat
    float4 bb0 = *(const float4*)(b2 + (size_t)e * H_DIM + c0);
    float4 bb1 = *(const float4*)(b2 + (size_t)e * H_DIM + 128 + c0);
    #pragma unroll
    for (int i = 0; i < 8; ++i) {
        int r = i * 8 + ty;
        float4 t0, t1;
        t0.x = tanhf(acc[i][0] + bb0.x); t0.y = tanhf(acc[i][1] + bb0.y);
        t0.z = tanhf(acc[i][2] + bb0.z); t0.w = tanhf(acc[i][3] + bb0.w);
        t1.x = tanhf(acc[i][4] + bb1.x); t1.y = tanhf(acc[i][5] + bb1.y);
        t1.z = tanhf(acc[i][6] + bb1.z); t1.w = tanhf(acc[i][7] + bb1.w);
        float* dst = g_H + (size_t)(b0 + r) * K_CAT + e * H_DIM;
        *(float4*)(dst + c0)       = t0;
        *(float4*)(dst + 128 + c0) = t1;
    }
}

// ---------------------------------------------------------------------------
// Pass 2: Out[b][q] = (1/8) * ( Hcat[b,:] @ Wt[:,q] + sum_e bt[e][q] )
// Wt viewed as [2048, N] row-major (contiguous for both Wg and Wf).
// CTA tile 128 x TN, K-chunks of 32, cp.async double-buffered.
// Threads: tx=tid%16, ty=tid/16; rows r=i*16+ty (delta-1 between warp-half ty's
// with A-stride 36 -> conflict-free); cols tx*4 (+64 for second group).
// ---------------------------------------------------------------------------
template<int TN>
__global__ void __launch_bounds__(256, 2) k_out(
    const float* __restrict__ Wt, const float* __restrict__ bt,
    float* __restrict__ out, int N)
{
    constexpr int NG = TN / 64;
    constexpr int AS = 36;                        // padded A stride
    extern __shared__ float sm[];
    float* sA0 = sm;
    float* sA1 = sm + 128 * AS;
    float* sB0 = sm + 2 * 128 * AS;
    float* sB1 = sB0 + 32 * TN;

    const int tid = threadIdx.x;
    const int tx = tid & 15, ty = tid >> 4;
    const int bm = blockIdx.x, bn = blockIdx.y;
    const int c0 = tx * 4;
    const float* Abase = g_H + (size_t)bm * 128 * K_CAT;
    const float* Bbase = Wt + (size_t)bn * TN;

    auto loadA = [&](float* buf, int k0) {
        #pragma unroll
        for (int j = 0; j < 4; ++j) {
            int lin = j * 256 + tid, row = lin >> 3, seg = lin & 7;
            cp16(buf + row * AS + seg * 4, Abase + (size_t)row * K_CAT + k0 + seg * 4);
        }
    };
    auto loadB = [&](float* buf, int k0) {
        #pragma unroll
        for (int j = 0; j < TN / 32; ++j) {
            int lin = j * 256 + tid;
            int row = lin / (TN / 4), seg = lin % (TN / 4);
            cp16(buf + row * TN + seg * 4, Bbase + (size_t)(k0 + row) * N + seg * 4);
        }
    };

    loadA(sA0, 0); loadB(sB0, 0); cp_commit();

    float acc[8][NG * 4] = {};
    const int NCH = K_CAT / 32;

    for (int kc = 0; kc < NCH; ++kc) {
        if (kc + 1 < NCH) {
            loadA(((kc + 1) & 1) ? sA1 : sA0, (kc + 1) * 32);
            loadB(((kc + 1) & 1) ? sB1 : sB0, (kc + 1) * 32);
            cp_commit(); cp_wait<1>();
        } else {
            cp_wait<0>();
        }
        __syncthreads();
        const float* cA = (kc & 1) ? sA1 : sA0;
        const float* cB = (kc & 1) ? sB1 : sB0;
        #pragma unroll 4
        for (int kk = 0; kk < 32; ++kk) {
            float a[8];
            #pragma unroll
            for (int i = 0; i < 8; ++i) a[i] = cA[(i * 16 + ty) * AS + kk];
            #pragma unroll
            for (int g = 0; g < NG; ++g) {
                float4 v = *(const float4*)(cB + kk * TN + g * 64 + c0);
                #pragma unroll
                for (int i = 0; i < 8; ++i) {
                    acc[i][g * 4 + 0] += a[i] * v.x;
                    acc[i][g * 4 + 1] += a[i] * v.y;
                    acc[i][g * 4 + 2] += a[i] * v.z;
                    acc[i][g * 4 + 3] += a[i] * v.w;
                }
            }
        }
        __syncthreads();
    }

    #pragma unroll
    for (int g = 0; g < NG; ++g) {
        int q0 = bn * TN + g * 64 + c0;
        float4 bs = make_float4(0.f, 0.f, 0.f, 0.f);
        #pragma unroll
        for (int e = 0; e < E_DIM; ++e) {
            float4 bv = *(const float4*)(bt + (size_t)e * N + q0);
            bs.x += bv.x; bs.y += bv.y; bs.z += bv.z; bs.w += bv.w;
        }
        #pragma unroll
        for (int i = 0; i < 8; ++i) {
            size_t r = (size_t)bm * 128 + i * 16 + ty;
            float4 o;
            o.x = 0.125f * (acc[i][g * 4 + 0] + bs.x);
            o.y = 0.125f * (acc[i][g * 4 + 1] + bs.y);
            o.z = 0.125f * (acc[i][g * 4 + 2] + bs.z);
            o.w = 0.125f * (acc[i][g * 4 + 3] + bs.w);
            *(float4*)(out + r * N + q0) = o;
        }
    }
}

// ---------------------------------------------------------------------------
extern "C" void kernel_launch(void* const* d_in, const int* in_sizes, int n_in,
                              void* d_out, int out_size)
{
    const float* state = (const float*)d_in[0];
    const float* W1    = (const float*)d_in[1];
    const float* b1    = (const float*)d_in[2];
    const float* W2    = (const float*)d_in[3];
    const float* b2    = (const float*)d_in[4];
    const float* Wf    = (const float*)d_in[5];
    const float* bf    = (const float*)d_in[6];
    const float* Wg    = (const float*)d_in[7];
    const float* bg    = (const float*)d_in[8];

    float* out   = (float*)d_out;
    float* out_f = out;                              // f_mean [B, S]
    float* out_g = out + (size_t)B_DIM * S_DIM;      // g_mean [B, S*A]

    const int smem1  = 49152 * 4;                          // 192 KB
    const int smem_g = (2 * 128 * 36 + 2 * 32 * 128) * 4;  // 68 KB
    const int smem_f = (2 * 128 * 36 + 2 * 32 * 64) * 4;   // 52 KB

    cudaFuncSetAttribute(k_fused12, cudaFuncAttributeMaxDynamicSharedMemorySize, smem1);
    cudaFuncSetAttribute(k_out<128>, cudaFuncAttributeMaxDynamicSharedMemorySize, smem_g);
    cudaFuncSetAttribute(k_out<64>,  cudaFuncAttributeMaxDynamicSharedMemorySize, smem_f);

    k_fused12<<<dim3(B_DIM / 64, E_DIM), 256, smem1>>>(state, W1, b1, W2, b2);
    k_out<128><<<dim3(B_DIM / 128, (S_DIM * A_DIM) / 128), 256, smem_g>>>(
        Wg, bg, out_g, S_DIM * A_DIM);
    k_out<64><<<dim3(B_DIM / 128, 1), 256, smem_f>>>(Wf, bf, out_f, S_DIM);
}

// round 3
// speedup vs baseline: 2.2116x; 2.2116x over previous
#include <cuda_runtime.h>
#include <math.h>
#include <stdint.h>

#define B_DIM 16384
#define S_DIM 64
#define A_DIM 16
#define H_DIM 256
#define E_DIM 8
#define K_CAT 2048   // E * H
#define N_G   1024   // S*A
#define N_F   64

// scratch
__device__ float g_H[(size_t)B_DIM * K_CAT];       // Hcat (tf32-rounded), 134 MB
__device__ float g_WgT[(size_t)N_G * K_CAT];       // Wg^T K-major, tf32-rounded
__device__ float g_WfT[(size_t)N_F * K_CAT];       // Wf^T K-major, tf32-rounded
__device__ float g_bsum[N_G + N_F];                // sum_e bias

// ---------------------------------------------------------------- helpers
__device__ __forceinline__ void cp16(void* dst, const float* src) {
    unsigned d = (unsigned)__cvta_generic_to_shared(dst);
    asm volatile("cp.async.cg.shared.global [%0], [%1], 16;" :: "r"(d), "l"(src));
}
__device__ __forceinline__ void cp_commit() { asm volatile("cp.async.commit_group;"); }
template<int N> __device__ __forceinline__ void cp_wait() {
    asm volatile("cp.async.wait_group %0;" :: "n"(N));
}
__device__ __forceinline__ float f2tf32(float x) {
    unsigned u;
    asm("cvt.rna.tf32.f32 %0, %1;" : "=r"(u) : "f"(x));
    return __uint_as_float(u);
}
__device__ __forceinline__ void mma_tf32(float* d, const uint32_t* a, const uint32_t* b) {
    asm volatile(
        "mma.sync.aligned.m16n8k8.row.col.f32.tf32.tf32.f32 "
        "{%0,%1,%2,%3},{%4,%5,%6,%7},{%8,%9},{%0,%1,%2,%3};"
        : "+f"(d[0]), "+f"(d[1]), "+f"(d[2]), "+f"(d[3])
        : "r"(a[0]), "r"(a[1]), "r"(a[2]), "r"(a[3]), "r"(b[0]), "r"(b[1]));
}

// ---------------------------------------------------------------------------
// Pass 1 (SIMT, unchanged): per (64-row batch tile, member e):
//   h2 = tanh(tanh(state@W1+b1)@W2+b2) -> g_H (tf32-rounded)
// ---------------------------------------------------------------------------
__global__ void __launch_bounds__(256, 1) k_fused12(
    const float* __restrict__ state, const float* __restrict__ W1,
    const float* __restrict__ b1,    const float* __restrict__ W2,
    const float* __restrict__ b2)
{
    extern __shared__ float sm[];
    float* sS  = sm;
    float* sW1 = sm + 4096;
    float* sH1 = sm + 32768;
    float* wb0 = sm;
    float* wb1 = sm + 16384;

    const int tid = threadIdx.x;
    const int tx = tid & 31, ty = tid >> 5;
    const int b0 = blockIdx.x * 64;
    const int e  = blockIdx.y;
    const int c0 = tx * 4;

    #pragma unroll
    for (int j = 0; j < 4; ++j) {
        int lin = j * 256 + tid, row = lin >> 4, seg = lin & 15;
        cp16(sS + row * 64 + seg * 4, state + (size_t)(b0 + row) * S_DIM + seg * 4);
    }
    const float* W1e = W1 + (size_t)e * S_DIM * H_DIM;
    #pragma unroll
    for (int j = 0; j < 16; ++j) {
        int lin = j * 256 + tid, row = lin >> 6, seg = lin & 63;
        cp16(sW1 + row * 256 + seg * 4, W1e + row * 256 + seg * 4);
    }
    cp_commit(); cp_wait<0>(); __syncthreads();

    float acc[8][8];
    #pragma unroll
    for (int i = 0; i < 8; ++i)
        #pragma unroll
        for (int j = 0; j < 8; ++j) acc[i][j] = 0.f;

    #pragma unroll 8
    for (int k = 0; k < 64; ++k) {
        float4 v0 = *(const float4*)(sW1 + k * 256 + c0);
        float4 v1 = *(const float4*)(sW1 + k * 256 + 128 + c0);
        #pragma unroll
        for (int i = 0; i < 8; ++i) {
            float a = sS[(i * 8 + ty) * 64 + k];
            acc[i][0] += a * v0.x; acc[i][1] += a * v0.y;
            acc[i][2] += a * v0.z; acc[i][3] += a * v0.w;
            acc[i][4] += a * v1.x; acc[i][5] += a * v1.y;
            acc[i][6] += a * v1.z; acc[i][7] += a * v1.w;
        }
    }
    __syncthreads();

    {
        float4 bb0 = *(const float4*)(b1 + (size_t)e * H_DIM + c0);
        float4 bb1 = *(const float4*)(b1 + (size_t)e * H_DIM + 128 + c0);
        #pragma unroll
        for (int i = 0; i < 8; ++i) {
            int r = i * 8 + ty;
            float4 t0, t1;
            t0.x = tanhf(acc[i][0] + bb0.x); t0.y = tanhf(acc[i][1] + bb0.y);
            t0.z = tanhf(acc[i][2] + bb0.z); t0.w = tanhf(acc[i][3] + bb0.w);
            t1.x = tanhf(acc[i][4] + bb1.x); t1.y = tanhf(acc[i][5] + bb1.y);
            t1.z = tanhf(acc[i][6] + bb1.z); t1.w = tanhf(acc[i][7] + bb1.w);
            *(float4*)(sH1 + r * 256 + c0)       = t0;
            *(float4*)(sH1 + r * 256 + 128 + c0) = t1;
        }
    }
    __syncthreads();

    const float* W2e = W2 + (size_t)e * H_DIM * H_DIM;
    #pragma unroll
    for (int j = 0; j < 16; ++j) {
        int lin = j * 256 + tid, row = lin >> 6, seg = lin & 63;
        cp16(wb0 + row * 256 + seg * 4, W2e + row * 256 + seg * 4);
    }
    cp_commit();

    #pragma unroll
    for (int i = 0; i < 8; ++i)
        #pragma unroll
        for (int j = 0; j < 8; ++j) acc[i][j] = 0.f;

    for (int kc = 0; kc < 4; ++kc) {
        if (kc < 3) {
            float* nb = ((kc + 1) & 1) ? wb1 : wb0;
            const float* src = W2e + (size_t)(kc + 1) * 64 * 256;
            #pragma unroll
            for (int j = 0; j < 16; ++j) {
                int lin = j * 256 + tid, row = lin >> 6, seg = lin & 63;
                cp16(nb + row * 256 + seg * 4, src + row * 256 + seg * 4);
            }
            cp_commit(); cp_wait<1>();
        } else {
            cp_wait<0>();
        }
        __syncthreads();
        const float* sW2 = (kc & 1) ? wb1 : wb0;
        const int kbase = kc * 64;
        #pragma unroll 8
        for (int kk = 0; kk < 64; ++kk) {
            float4 v0 = *(const float4*)(sW2 + kk * 256 + c0);
            float4 v1 = *(const float4*)(sW2 + kk * 256 + 128 + c0);
            #pragma unroll
            for (int i = 0; i < 8; ++i) {
                float a = sH1[(i * 8 + ty) * 256 + kbase + kk];
                acc[i][0] += a * v0.x; acc[i][1] += a * v0.y;
                acc[i][2] += a * v0.z; acc[i][3] += a * v0.w;
                acc[i][4] += a * v1.x; acc[i][5] += a * v1.y;
                acc[i][6] += a * v1.z; acc[i][7] += a * v1.w;
            }
        }
        __syncthreads();
    }

    float4 bb0 = *(const float4*)(b2 + (size_t)e * H_DIM + c0);
    float4 bb1 = *(const float4*)(b2 + (size_t)e * H_DIM + 128 + c0);
    #pragma unroll
    for (int i = 0; i < 8; ++i) {
        int r = i * 8 + ty;
        float4 t0, t1;
        t0.x = f2tf32(tanhf(acc[i][0] + bb0.x)); t0.y = f2tf32(tanhf(acc[i][1] + bb0.y));
        t0.z = f2tf32(tanhf(acc[i][2] + bb0.z)); t0.w = f2tf32(tanhf(acc[i][3] + bb0.w));
        t1.x = f2tf32(tanhf(acc[i][4] + bb1.x)); t1.y = f2tf32(tanhf(acc[i][5] + bb1.y));
        t1.z = f2tf32(tanhf(acc[i][6] + bb1.z)); t1.w = f2tf32(tanhf(acc[i][7] + bb1.w));
        float* dst = g_H + (size_t)(b0 + r) * K_CAT + e * H_DIM;
        *(float4*)(dst + c0)       = t0;
        *(float4*)(dst + 128 + c0) = t1;
    }
}

// ---------------------------------------------------------------------------
// Prep: transpose W [K_CAT, N] -> WT [N, K_CAT] with tf32 rounding
// ---------------------------------------------------------------------------
__global__ void k_tr(const float* __restrict__ W, float* __restrict__ WT, int N) {
    __shared__ float t[32][33];
    int k0 = blockIdx.x * 32, n0 = blockIdx.y * 32;
    int x = threadIdx.x, y = threadIdx.y;  // 32 x 8
    #pragma unroll
    for (int i = 0; i < 32; i += 8)
        t[y + i][x] = W[(size_t)(k0 + y + i) * N + n0 + x];
    __syncthreads();
    #pragma unroll
    for (int i = 0; i < 32; i += 8)
        WT[(size_t)(n0 + y + i) * K_CAT + k0 + x] = f2tf32(t[x][y + i]);
}

__global__ void k_bias(const float* __restrict__ bg, const float* __restrict__ bf) {
    int q = blockIdx.x * 256 + threadIdx.x;
    if (q < N_G) {
        float s = 0.f;
        #pragma unroll
        for (int e = 0; e < E_DIM; ++e) s += bg[(size_t)e * N_G + q];
        g_bsum[q] = s;
    } else if (q < N_G + N_F) {
        int qq = q - N_G;
        float s = 0.f;
        #pragma unroll
        for (int e = 0; e < E_DIM; ++e) s += bf[(size_t)e * N_F + qq];
        g_bsum[q] = s;
    }
}

// ---------------------------------------------------------------------------
// Pass 2: mma.sync tf32 GEMM.
// out[m][n] = 0.125*(sum_k Hcat[m,k]*WT[n,k] + bsum[n])
// CTA tile 128 x TN. 4 warps (2x2): warp tile 64 x TN/2.
// m16n8k8 tiles: 4 m-tiles x NT n-tiles per warp. K chunks of 32, 2-stage
// cp.async. SMEM stride 36 -> conflict-free fragment lds.32.
// ---------------------------------------------------------------------------
template<int TN>
__global__ void __launch_bounds__(128, 2) k_mma(
    const float* __restrict__ WT, const float* __restrict__ bsum,
    float* __restrict__ out, int Ntot)
{
    constexpr int NT  = TN / 16;   // n-tiles per warp (warp tile n = TN/2)
    constexpr int AST = 36;        // smem stride (floats)
    constexpr int NCH = K_CAT / 32;

    extern __shared__ float sm[];
    float* sA0 = sm;
    float* sA1 = sA0 + 128 * AST;
    float* sB0 = sA1 + 128 * AST;
    float* sB1 = sB0 + TN * AST;
    float* sBias = sB1 + TN * AST;

    const int tid = threadIdx.x;
    const int lane = tid & 31, w = tid >> 5;
    const int wm = w >> 1, wn = w & 1;
    const int g = lane >> 2, tg = lane & 3;
    const int bm = blockIdx.x, bn = blockIdx.y;

    const float* Abase = g_H + (size_t)bm * 128 * K_CAT;
    const float* Bbase = WT + (size_t)bn * TN * K_CAT;

    if (tid < TN) sBias[tid] = bsum[(size_t)bn * TN + tid];

    auto loadA = [&](float* buf, int kc) {
        #pragma unroll
        for (int j = 0; j < 8; ++j) {
            int lin = j * 128 + tid, row = lin >> 3, seg = lin & 7;
            cp16(buf + row * AST + seg * 4, Abase + (size_t)row * K_CAT + kc * 32 + seg * 4);
        }
    };
    auto loadB = [&](float* buf, int kc) {
        #pragma unroll
        for (int j = 0; j < TN / 16; ++j) {
            int lin = j * 128 + tid, row = lin >> 3, seg = lin & 7;
            cp16(buf + row * AST + seg * 4, Bbase + (size_t)row * K_CAT + kc * 32 + seg * 4);
        }
    };

    float acc[4][NT][4];
    #pragma unroll
    for (int t = 0; t < 4; ++t)
        #pragma unroll
        for (int u = 0; u < NT; ++u)
            #pragma unroll
            for (int v = 0; v < 4; ++v) acc[t][u][v] = 0.f;

    loadA(sA0, 0); loadB(sB0, 0); cp_commit();

    for (int kc = 0; kc < NCH; ++kc) {
        if (kc + 1 < NCH) {
            loadA((kc & 1) ? sA0 : sA1, kc + 1);
            loadB((kc & 1) ? sB0 : sB1, kc + 1);
            cp_commit(); cp_wait<1>();
        } else {
            cp_wait<0>();
        }
        __syncthreads();
        const float* cA = (kc & 1) ? sA1 : sA0;
        const float* cB = (kc & 1) ? sB1 : sB0;

        #pragma unroll
        for (int ks = 0; ks < 4; ++ks) {
            const int k0 = ks * 8;
            uint32_t a[4][4];
            #pragma unroll
            for (int t = 0; t < 4; ++t) {
                const float* ap = cA + (wm * 64 + t * 16 + g) * AST + k0 + tg;
                a[t][0] = __float_as_uint(ap[0]);
                a[t][1] = __float_as_uint(ap[8 * AST]);
                a[t][2] = __float_as_uint(ap[4]);
                a[t][3] = __float_as_uint(ap[8 * AST + 4]);
            }
            uint32_t b[NT][2];
            #pragma unroll
            for (int u = 0; u < NT; ++u) {
                const float* bp = cB + (wn * (TN / 2) + u * 8 + g) * AST + k0 + tg;
                b[u][0] = __float_as_uint(bp[0]);
                b[u][1] = __float_as_uint(bp[4]);
            }
            #pragma unroll
            for (int t = 0; t < 4; ++t)
                #pragma unroll
                for (int u = 0; u < NT; ++u)
                    mma_tf32(acc[t][u], a[t], b[u]);
        }
        __syncthreads();
    }

    // epilogue: c0 (row=g, col=2tg), c1 (col+1), c2/c3 at row+8
    #pragma unroll
    for (int t = 0; t < 4; ++t) {
        size_t r0 = (size_t)bm * 128 + wm * 64 + t * 16 + g;
        #pragma unroll
        for (int u = 0; u < NT; ++u) {
            int cl = wn * (TN / 2) + u * 8 + tg * 2;
            size_t c = (size_t)bn * TN + cl;
            float bs0 = sBias[cl], bs1 = sBias[cl + 1];
            float2 v0, v1;
            v0.x = 0.125f * (acc[t][u][0] + bs0);
            v0.y = 0.125f * (acc[t][u][1] + bs1);
            v1.x = 0.125f * (acc[t][u][2] + bs0);
            v1.y = 0.125f * (acc[t][u][3] + bs1);
            *(float2*)(out + r0 * Ntot + c)       = v0;
            *(float2*)(out + (r0 + 8) * Ntot + c) = v1;
        }
    }
}

// ---------------------------------------------------------------------------
extern "C" void kernel_launch(void* const* d_in, const int* in_sizes, int n_in,
                              void* d_out, int out_size)
{
    const float* state = (const float*)d_in[0];
    const float* W1    = (const float*)d_in[1];
    const float* b1    = (const float*)d_in[2];
    const float* W2    = (const float*)d_in[3];
    const float* b2    = (const float*)d_in[4];
    const float* Wf    = (const float*)d_in[5];
    const float* bf    = (const float*)d_in[6];
    const float* Wg    = (const float*)d_in[7];
    const float* bg    = (const float*)d_in[8];

    float* out   = (float*)d_out;
    float* out_f = out;                              // f_mean [B, 64]
    float* out_g = out + (size_t)B_DIM * S_DIM;      // g_mean [B, 1024]

    float* WgT; cudaGetSymbolAddress((void**)&WgT, g_WgT);
    float* WfT; cudaGetSymbolAddress((void**)&WfT, g_WfT);
    float* bsm; cudaGetSymbolAddress((void**)&bsm, g_bsum);

    const int smem1 = 49152 * 4;                                   // 192 KB
    const int smemG = (2 * 128 * 36 + 2 * 128 * 36 + 128) * 4;     // ~72.5 KB
    const int smemF = (2 * 128 * 36 + 2 * 64 * 36 + 64) * 4;       // ~54.5 KB

    cudaFuncSetAttribute(k_fused12, cudaFuncAttributeMaxDynamicSharedMemorySize, smem1);
    cudaFuncSetAttribute(k_mma<128>, cudaFuncAttributeMaxDynamicSharedMemorySize, smemG);
    cudaFuncSetAttribute(k_mma<64>,  cudaFuncAttributeMaxDynamicSharedMemorySize, smemF);

    k_bias<<<(N_G + N_F + 255) / 256, 256>>>(bg, bf);
    k_tr<<<dim3(K_CAT / 32, N_G / 32), dim3(32, 8)>>>(Wg, WgT, N_G);
    k_tr<<<dim3(K_CAT / 32, N_F / 32), dim3(32, 8)>>>(Wf, WfT, N_F);

    k_fused12<<<dim3(B_DIM / 64, E_DIM), 256, smem1>>>(state, W1, b1, W2, b2);

    k_mma<128><<<dim3(B_DIM / 128, N_G / 128), 128, smemG>>>(WgT, bsm, out_g, N_G);
    k_mma<64><<<dim3(B_DIM / 128, 1), 128, smemF>>>(WfT, bsm + N_G, out_f, N_F);
}

// round 4
// speedup vs baseline: 3.1993x; 1.4466x over previous
#include <cuda_runtime.h>
#include <math.h>
#include <stdint.h>

#define B_DIM 16384
#define S_DIM 64
#define A_DIM 16
#define H_DIM 256
#define E_DIM 8
#define K_CAT 2048   // E * H
#define N_G   1024   // S*A
#define N_F   64

// scratch
__device__ float g_H[(size_t)B_DIM * K_CAT];       // Hcat (tf32-rounded), 134 MB
__device__ float g_WgT[(size_t)N_G * K_CAT];       // Wg^T K-major, tf32
__device__ float g_WfT[(size_t)N_F * K_CAT];       // Wf^T K-major, tf32
__device__ float g_W1T[(size_t)E_DIM * H_DIM * S_DIM];  // [e][h][s] tf32
__device__ float g_W2T[(size_t)E_DIM * H_DIM * H_DIM];  // [e][hout][hin] tf32
__device__ float g_bsum[N_G + N_F];                // sum_e bias

// ---------------------------------------------------------------- helpers
__device__ __forceinline__ void cp16(void* dst, const float* src) {
    unsigned d = (unsigned)__cvta_generic_to_shared(dst);
    asm volatile("cp.async.cg.shared.global [%0], [%1], 16;" :: "r"(d), "l"(src));
}
__device__ __forceinline__ void cp_commit() { asm volatile("cp.async.commit_group;"); }
template<int N> __device__ __forceinline__ void cp_wait() {
    asm volatile("cp.async.wait_group %0;" :: "n"(N));
}
__device__ __forceinline__ float f2tf32(float x) {
    unsigned u;
    asm("cvt.rna.tf32.f32 %0, %1;" : "=r"(u) : "f"(x));
    return __uint_as_float(u);
}
__device__ __forceinline__ void mma_tf32(float* d, const uint32_t* a, const uint32_t* b) {
    asm volatile(
        "mma.sync.aligned.m16n8k8.row.col.f32.tf32.tf32.f32 "
        "{%0,%1,%2,%3},{%4,%5,%6,%7},{%8,%9},{%0,%1,%2,%3};"
        : "+f"(d[0]), "+f"(d[1]), "+f"(d[2]), "+f"(d[3])
        : "r"(a[0]), "r"(a[1]), "r"(a[2]), "r"(a[3]), "r"(b[0]), "r"(b[1]));
}

// ---------------------------------------------------------------------------
// Prep: transpose W[z][K,N] -> WT[z][N,K] with tf32 rounding
// ---------------------------------------------------------------------------
__global__ void k_trw(const float* __restrict__ W, float* __restrict__ WT,
                      int K, int N) {
    __shared__ float t[32][33];
    const float* Wb = W + (size_t)blockIdx.z * K * N;
    float* WTb = WT + (size_t)blockIdx.z * K * N;
    int k0 = blockIdx.x * 32, n0 = blockIdx.y * 32;
    int x = threadIdx.x, y = threadIdx.y;  // 32 x 8
    #pragma unroll
    for (int i = 0; i < 32; i += 8)
        t[y + i][x] = Wb[(size_t)(k0 + y + i) * N + n0 + x];
    __syncthreads();
    #pragma unroll
    for (int i = 0; i < 32; i += 8)
        WTb[(size_t)(n0 + y + i) * K + k0 + x] = f2tf32(t[x][y + i]);
}

__global__ void k_bias(const float* __restrict__ bg, const float* __restrict__ bf) {
    int q = blockIdx.x * 256 + threadIdx.x;
    if (q < N_G) {
        float s = 0.f;
        #pragma unroll
        for (int e = 0; e < E_DIM; ++e) s += bg[(size_t)e * N_G + q];
        g_bsum[q] = s;
    } else if (q < N_G + N_F) {
        int qq = q - N_G;
        float s = 0.f;
        #pragma unroll
        for (int e = 0; e < E_DIM; ++e) s += bf[(size_t)e * N_F + qq];
        g_bsum[q] = s;
    }
}

// ---------------------------------------------------------------------------
// Pass 1 (tensorized): CTA = (128 batch rows, member e).
//   h1 = tanh(state @ W1 + b1); h2 = tanh(h1 @ W2 + b2) -> g_H[b][e*256+...]
// 8 warps (wm 0..1, wn 0..3), warp tile 64x64, m16n8k8 tf32 mma.
// SMEM strides: state/W1 68, h1 260, W2 chunk 36 (all => bank (4g+tg)%32,
// conflict-free fragment loads).
// ---------------------------------------------------------------------------
__global__ void __launch_bounds__(256, 1) k_mlp(
    const float* __restrict__ state, const float* __restrict__ b1,
    const float* __restrict__ b2)
{
    extern __shared__ float sm[];
    float* sS   = sm;                 // [128][68] phase 1
    float* sW1  = sm + 128 * 68;      // [256][68] phase 1
    float* sH   = sm;                 // [128][260] phase 2 (overwrites sS/sW1)
    float* sW2a = sm + 128 * 260;     // [256][36]
    float* sW2b = sW2a + 256 * 36;    // [256][36]

    const int tid = threadIdx.x;
    const int lane = tid & 31, w = tid >> 5;
    const int wm = w >> 2, wn = w & 3;
    const int g = lane >> 2, tg = lane & 3;
    const int b0 = blockIdx.x * 128;
    const int e  = blockIdx.y;

    const float* W1e = g_W1T + (size_t)e * H_DIM * S_DIM;   // [256][64]
    const float* W2e = g_W2T + (size_t)e * H_DIM * H_DIM;   // [256][256]

    auto loadW2 = [&](float* buf, int kc) {
        #pragma unroll
        for (int j = 0; j < 8; ++j) {
            int lin = j * 256 + tid, row = lin >> 3, seg = lin & 7;
            cp16(buf + row * 36 + seg * 4, W2e + (size_t)row * 256 + kc * 32 + seg * 4);
        }
    };

    // phase-1 loads
    #pragma unroll
    for (int j = 0; j < 8; ++j) {   // state: 128 x 64
        int lin = j * 256 + tid, row = lin >> 4, seg = lin & 15;
        cp16(sS + row * 68 + seg * 4, state + (size_t)(b0 + row) * S_DIM + seg * 4);
    }
    #pragma unroll
    for (int j = 0; j < 16; ++j) {  // W1T: 256 x 64
        int lin = j * 256 + tid, row = lin >> 4, seg = lin & 15;
        cp16(sW1 + row * 68 + seg * 4, W1e + (size_t)row * S_DIM + seg * 4);
    }
    cp_commit();
    loadW2(sW2a, 0); cp_commit();
    loadW2(sW2b, 1); cp_commit();
    cp_wait<2>(); __syncthreads();

    // round state to tf32 in smem
    #pragma unroll
    for (int j = 0; j < 32; ++j) {
        int idx = j * 256 + tid, row = idx >> 6, col = idx & 63;
        sS[row * 68 + col] = f2tf32(sS[row * 68 + col]);
    }
    __syncthreads();

    // ---- layer 1: K=64, 8 ksteps ----
    float acc[4][8][4];
    #pragma unroll
    for (int t = 0; t < 4; ++t)
        #pragma unroll
        for (int u = 0; u < 8; ++u)
            #pragma unroll
            for (int v = 0; v < 4; ++v) acc[t][u][v] = 0.f;

    #pragma unroll
    for (int ks = 0; ks < 8; ++ks) {
        const int k0 = ks * 8;
        uint32_t a[4][4];
        #pragma unroll
        for (int t = 0; t < 4; ++t) {
            const float* ap = sS + (wm * 64 + t * 16 + g) * 68 + k0 + tg;
            a[t][0] = __float_as_uint(ap[0]);
            a[t][1] = __float_as_uint(ap[8 * 68]);
            a[t][2] = __float_as_uint(ap[4]);
            a[t][3] = __float_as_uint(ap[8 * 68 + 4]);
        }
        uint32_t b[8][2];
        #pragma unroll
        for (int u = 0; u < 8; ++u) {
            const float* bp = sW1 + (wn * 64 + u * 8 + g) * 68 + k0 + tg;
            b[u][0] = __float_as_uint(bp[0]);
            b[u][1] = __float_as_uint(bp[4]);
        }
        #pragma unroll
        for (int t = 0; t < 4; ++t)
            #pragma unroll
            for (int u = 0; u < 8; ++u)
                mma_tf32(acc[t][u], a[t], b[u]);
    }
    __syncthreads();   // done reading sS / sW1

    // epilogue 1: tanh + bias -> sH (tf32-rounded)
    #pragma unroll
    for (int t = 0; t < 4; ++t) {
        int r = wm * 64 + t * 16 + g;
        #pragma unroll
        for (int u = 0; u < 8; ++u) {
            int cl = wn * 64 + u * 8 + tg * 2;
            float bb0 = b1[(size_t)e * H_DIM + cl];
            float bb1 = b1[(size_t)e * H_DIM + cl + 1];
            float2 v0, v1;
            v0.x = f2tf32(tanhf(acc[t][u][0] + bb0));
            v0.y = f2tf32(tanhf(acc[t][u][1] + bb1));
            v1.x = f2tf32(tanhf(acc[t][u][2] + bb0));
            v1.y = f2tf32(tanhf(acc[t][u][3] + bb1));
            *(float2*)(sH + r * 260 + cl)       = v0;
            *(float2*)(sH + (r + 8) * 260 + cl) = v1;
        }
    }
    __syncthreads();

    // ---- layer 2: K=256, 8 chunks of 32 ----
    #pragma unroll
    for (int t = 0; t < 4; ++t)
        #pragma unroll
        for (int u = 0; u < 8; ++u)
            #pragma unroll
            for (int v = 0; v < 4; ++v) acc[t][u][v] = 0.f;

    for (int kc = 0; kc < 8; ++kc) {
        if (kc < 7) cp_wait<1>(); else cp_wait<0>();
        __syncthreads();
        const float* cB = (kc & 1) ? sW2b : sW2a;
        #pragma unroll
        for (int ks = 0; ks < 4; ++ks) {
            const int k0 = kc * 32 + ks * 8;
            uint32_t a[4][4];
            #pragma unroll
            for (int t = 0; t < 4; ++t) {
                const float* ap = sH + (wm * 64 + t * 16 + g) * 260 + k0 + tg;
                a[t][0] = __float_as_uint(ap[0]);
                a[t][1] = __float_as_uint(ap[8 * 260]);
                a[t][2] = __float_as_uint(ap[4]);
                a[t][3] = __float_as_uint(ap[8 * 260 + 4]);
            }
            uint32_t b[8][2];
            #pragma unroll
            for (int u = 0; u < 8; ++u) {
                const float* bp = cB + (wn * 64 + u * 8 + g) * 36 + ks * 8 + tg;
                b[u][0] = __float_as_uint(bp[0]);
                b[u][1] = __float_as_uint(bp[4]);
            }
            #pragma unroll
            for (int t = 0; t < 4; ++t)
                #pragma unroll
                for (int u = 0; u < 8; ++u)
                    mma_tf32(acc[t][u], a[t], b[u]);
        }
        __syncthreads();    // buffer consumed; safe to refill
        if (kc + 2 < 8) {
            loadW2((kc & 1) ? sW2b : sW2a, kc + 2);
            cp_commit();
        }
    }

    // epilogue 2: tanh + bias -> g_H (tf32-rounded)
    #pragma unroll
    for (int t = 0; t < 4; ++t) {
        size_t r = (size_t)b0 + wm * 64 + t * 16 + g;
        #pragma unroll
        for (int u = 0; u < 8; ++u) {
            int cl = wn * 64 + u * 8 + tg * 2;
            float bb0 = b2[(size_t)e * H_DIM + cl];
            float bb1 = b2[(size_t)e * H_DIM + cl + 1];
            float2 v0, v1;
            v0.x = f2tf32(tanhf(acc[t][u][0] + bb0));
            v0.y = f2tf32(tanhf(acc[t][u][1] + bb1));
            v1.x = f2tf32(tanhf(acc[t][u][2] + bb0));
            v1.y = f2tf32(tanhf(acc[t][u][3] + bb1));
            float* dst = g_H + r * K_CAT + e * H_DIM + cl;
            *(float2*)dst = v0;
            *(float2*)(dst + 8 * K_CAT) = v1;
        }
    }
}

// ---------------------------------------------------------------------------
// Pass 2: mma.sync tf32 GEMM (unchanged from round 3).
// out[m][n] = 0.125*(sum_k Hcat[m,k]*WT[n,k] + bsum[n])
// ---------------------------------------------------------------------------
template<int TN>
__global__ void __launch_bounds__(128, 2) k_mma(
    const float* __restrict__ WT, const float* __restrict__ bsum,
    float* __restrict__ out, int Ntot)
{
    constexpr int NT  = TN / 16;
    constexpr int AST = 36;
    constexpr int NCH = K_CAT / 32;

    extern __shared__ float sm[];
    float* sA0 = sm;
    float* sA1 = sA0 + 128 * AST;
    float* sB0 = sA1 + 128 * AST;
    float* sB1 = sB0 + TN * AST;
    float* sBias = sB1 + TN * AST;

    const int tid = threadIdx.x;
    const int lane = tid & 31, w = tid >> 5;
    const int wm = w >> 1, wn = w & 1;
    const int g = lane >> 2, tg = lane & 3;
    const int bm = blockIdx.x, bn = blockIdx.y;

    const float* Abase = g_H + (size_t)bm * 128 * K_CAT;
    const float* Bbase = WT + (size_t)bn * TN * K_CAT;

    if (tid < TN) sBias[tid] = bsum[(size_t)bn * TN + tid];

    auto loadA = [&](float* buf, int kc) {
        #pragma unroll
        for (int j = 0; j < 8; ++j) {
            int lin = j * 128 + tid, row = lin >> 3, seg = lin & 7;
            cp16(buf + row * AST + seg * 4, Abase + (size_t)row * K_CAT + kc * 32 + seg * 4);
        }
    };
    auto loadB = [&](float* buf, int kc) {
        #pragma unroll
        for (int j = 0; j < TN / 16; ++j) {
            int lin = j * 128 + tid, row = lin >> 3, seg = lin & 7;
            cp16(buf + row * AST + seg * 4, Bbase + (size_t)row * K_CAT + kc * 32 + seg * 4);
        }
    };

    float acc[4][NT][4];
    #pragma unroll
    for (int t = 0; t < 4; ++t)
        #pragma unroll
        for (int u = 0; u < NT; ++u)
            #pragma unroll
            for (int v = 0; v < 4; ++v) acc[t][u][v] = 0.f;

    loadA(sA0, 0); loadB(sB0, 0); cp_commit();

    for (int kc = 0; kc < NCH; ++kc) {
        if (kc + 1 < NCH) {
            loadA((kc & 1) ? sA0 : sA1, kc + 1);
            loadB((kc & 1) ? sB0 : sB1, kc + 1);
            cp_commit(); cp_wait<1>();
        } else {
            cp_wait<0>();
        }
        __syncthreads();
        const float* cA = (kc & 1) ? sA1 : sA0;
        const float* cB = (kc & 1) ? sB1 : sB0;

        #pragma unroll
        for (int ks = 0; ks < 4; ++ks) {
            const int k0 = ks * 8;
            uint32_t a[4][4];
            #pragma unroll
            for (int t = 0; t < 4; ++t) {
                const float* ap = cA + (wm * 64 + t * 16 + g) * AST + k0 + tg;
                a[t][0] = __float_as_uint(ap[0]);
                a[t][1] = __float_as_uint(ap[8 * AST]);
                a[t][2] = __float_as_uint(ap[4]);
                a[t][3] = __float_as_uint(ap[8 * AST + 4]);
            }
            uint32_t b[NT][2];
            #pragma unroll
            for (int u = 0; u < NT; ++u) {
                const float* bp = cB + (wn * (TN / 2) + u * 8 + g) * AST + k0 + tg;
                b[u][0] = __float_as_uint(bp[0]);
                b[u][1] = __float_as_uint(bp[4]);
            }
            #pragma unroll
            for (int t = 0; t < 4; ++t)
                #pragma unroll
                for (int u = 0; u < NT; ++u)
                    mma_tf32(acc[t][u], a[t], b[u]);
        }
        __syncthreads();
    }

    #pragma unroll
    for (int t = 0; t < 4; ++t) {
        size_t r0 = (size_t)bm * 128 + wm * 64 + t * 16 + g;
        #pragma unroll
        for (int u = 0; u < NT; ++u) {
            int cl = wn * (TN / 2) + u * 8 + tg * 2;
            size_t c = (size_t)bn * TN + cl;
            float bs0 = sBias[cl], bs1 = sBias[cl + 1];
            float2 v0, v1;
            v0.x = 0.125f * (acc[t][u][0] + bs0);
            v0.y = 0.125f * (acc[t][u][1] + bs1);
            v1.x = 0.125f * (acc[t][u][2] + bs0);
            v1.y = 0.125f * (acc[t][u][3] + bs1);
            *(float2*)(out + r0 * Ntot + c)       = v0;
            *(float2*)(out + (r0 + 8) * Ntot + c) = v1;
        }
    }
}

// ---------------------------------------------------------------------------
extern "C" void kernel_launch(void* const* d_in, const int* in_sizes, int n_in,
                              void* d_out, int out_size)
{
    const float* state = (const float*)d_in[0];
    const float* W1    = (const float*)d_in[1];
    const float* b1    = (const float*)d_in[2];
    const float* W2    = (const float*)d_in[3];
    const float* b2    = (const float*)d_in[4];
    const float* Wf    = (const float*)d_in[5];
    const float* bf    = (const float*)d_in[6];
    const float* Wg    = (const float*)d_in[7];
    const float* bg    = (const float*)d_in[8];

    float* out   = (float*)d_out;
    float* out_f = out;                              // f_mean [B, 64]
    float* out_g = out + (size_t)B_DIM * S_DIM;      // g_mean [B, 1024]

    float* WgT; cudaGetSymbolAddress((void**)&WgT, g_WgT);
    float* WfT; cudaGetSymbolAddress((void**)&WfT, g_WfT);
    float* W1T; cudaGetSymbolAddress((void**)&W1T, g_W1T);
    float* W2T; cudaGetSymbolAddress((void**)&W2T, g_W2T);
    float* bsm; cudaGetSymbolAddress((void**)&bsm, g_bsum);

    const int smemM = (128 * 260 + 2 * 256 * 36) * 4;            // 206,848
    const int smemG = (2 * 128 * 36 + 2 * 128 * 36 + 128) * 4;   // ~73 KB
    const int smemF = (2 * 128 * 36 + 2 * 64 * 36 + 64) * 4;     // ~55 KB

    cudaFuncSetAttribute(k_mlp, cudaFuncAttributeMaxDynamicSharedMemorySize, smemM);
    cudaFuncSetAttribute(k_mma<128>, cudaFuncAttributeMaxDynamicSharedMemorySize, smemG);
    cudaFuncSetAttribute(k_mma<64>,  cudaFuncAttributeMaxDynamicSharedMemorySize, smemF);

    k_bias<<<(N_G + N_F + 255) / 256, 256>>>(bg, bf);
    k_trw<<<dim3(K_CAT / 32, N_G / 32, 1), dim3(32, 8)>>>(Wg, WgT, K_CAT, N_G);
    k_trw<<<dim3(K_CAT / 32, N_F / 32, 1), dim3(32, 8)>>>(Wf, WfT, K_CAT, N_F);
    k_trw<<<dim3(S_DIM / 32, H_DIM / 32, E_DIM), dim3(32, 8)>>>(W1, W1T, S_DIM, H_DIM);
    k_trw<<<dim3(H_DIM / 32, H_DIM / 32, E_DIM), dim3(32, 8)>>>(W2, W2T, H_DIM, H_DIM);

    k_mlp<<<dim3(B_DIM / 128, E_DIM), 256, smemM>>>(state, b1, b2);

    k_mma<128><<<dim3(B_DIM / 128, N_G / 128), 128, smemG>>>(WgT, bsm, out_g, N_G);
    k_mma<64><<<dim3(B_DIM / 128, 1), 128, smemF>>>(WfT, bsm + N_G, out_f, N_F);
}

// round 5
// speedup vs baseline: 5.8077x; 1.8153x over previous
#include <cuda_runtime.h>
#include <cuda_fp16.h>
#include <math.h>
#include <stdint.h>

#define B_DIM 16384
#define S_DIM 64
#define A_DIM 16
#define H_DIM 256
#define E_DIM 8
#define K_CAT 2048   // E * H
#define N_G   1024   // S*A
#define N_F   64

// scratch (all fp16 operands)
__device__ __half g_H[(size_t)B_DIM * K_CAT];            // Hcat, 67 MB
__device__ __half g_Sh[(size_t)B_DIM * S_DIM];           // state fp16
__device__ __half g_WgT[(size_t)N_G * K_CAT];            // Wg^T [n][k]
__device__ __half g_WfT[(size_t)N_F * K_CAT];            // Wf^T [n][k]
__device__ __half g_W1T[(size_t)E_DIM * H_DIM * S_DIM];  // [e][h][s]
__device__ __half g_W2T[(size_t)E_DIM * H_DIM * H_DIM];  // [e][hout][hin]
__device__ float  g_bsum[N_G + N_F];                     // sum_e bias (fp32)

// ---------------------------------------------------------------- helpers
__device__ __forceinline__ void cp16(void* dst, const void* src) {
    unsigned d = (unsigned)__cvta_generic_to_shared(dst);
    asm volatile("cp.async.cg.shared.global [%0], [%1], 16;" :: "r"(d), "l"(src));
}
__device__ __forceinline__ void cp_commit() { asm volatile("cp.async.commit_group;"); }
template<int N> __device__ __forceinline__ void cp_wait() {
    asm volatile("cp.async.wait_group %0;" :: "n"(N));
}
// m16n8k16 fp16 -> fp32 acc
__device__ __forceinline__ void mma_f16(float* d, const uint32_t* a, const uint32_t* b) {
    asm volatile(
        "mma.sync.aligned.m16n8k16.row.col.f32.f16.f16.f32 "
        "{%0,%1,%2,%3},{%4,%5,%6,%7},{%8,%9},{%0,%1,%2,%3};"
        : "+f"(d[0]), "+f"(d[1]), "+f"(d[2]), "+f"(d[3])
        : "r"(a[0]), "r"(a[1]), "r"(a[2]), "r"(a[3]), "r"(b[0]), "r"(b[1]));
}

// ---------------------------------------------------------------------------
// Prep kernels
// ---------------------------------------------------------------------------
__global__ void k_cvt_state(const float* __restrict__ s) {
    int i = blockIdx.x * 256 + threadIdx.x;        // B*S/4 iterations of 4
    float4 v = *(const float4*)(s + (size_t)i * 4);
    __half2 h0 = __floats2half2_rn(v.x, v.y);
    __half2 h1 = __floats2half2_rn(v.z, v.w);
    *(uint2*)(g_Sh + (size_t)i * 4) = make_uint2(
        *(uint32_t*)&h0, *(uint32_t*)&h1);
}

__global__ void k_trw(const float* __restrict__ W, __half* __restrict__ WT,
                      int K, int N) {
    __shared__ float t[32][33];
    const float* Wb = W + (size_t)blockIdx.z * K * N;
    __half* WTb = WT + (size_t)blockIdx.z * K * N;
    int k0 = blockIdx.x * 32, n0 = blockIdx.y * 32;
    int x = threadIdx.x, y = threadIdx.y;  // 32 x 8
    #pragma unroll
    for (int i = 0; i < 32; i += 8)
        t[y + i][x] = Wb[(size_t)(k0 + y + i) * N + n0 + x];
    __syncthreads();
    #pragma unroll
    for (int i = 0; i < 32; i += 8)
        WTb[(size_t)(n0 + y + i) * K + k0 + x] = __float2half_rn(t[x][y + i]);
}

__global__ void k_bias(const float* __restrict__ bg, const float* __restrict__ bf) {
    int q = blockIdx.x * 256 + threadIdx.x;
    if (q < N_G) {
        float s = 0.f;
        #pragma unroll
        for (int e = 0; e < E_DIM; ++e) s += bg[(size_t)e * N_G + q];
        g_bsum[q] = s;
    } else if (q < N_G + N_F) {
        int qq = q - N_G;
        float s = 0.f;
        #pragma unroll
        for (int e = 0; e < E_DIM; ++e) s += bf[(size_t)e * N_F + qq];
        g_bsum[q] = s;
    }
}

// ---------------------------------------------------------------------------
// Pass 1: CTA = (128 batch rows, member e). fp16 m16n8k16 MMA.
// 8 warps (wm 0..1, wn 0..3), warp tile 64x64.
// SMEM half strides: state/W1 72, h1 264, W2 chunk 72 (word-bank conflict-free).
// ---------------------------------------------------------------------------
__global__ void __launch_bounds__(256, 1) k_mlp(
    const float* __restrict__ b1, const float* __restrict__ b2)
{
    extern __shared__ __half smh[];
    __half* sS   = smh;                  // [128][72] phase 1
    __half* sW1  = smh + 128 * 72;       // [256][72] phase 1
    __half* sH   = smh;                  // [128][264] phase 2
    __half* sW2a = smh + 128 * 264;      // [256][72] (64-half chunk)
    __half* sW2b = sW2a + 256 * 72;

    const int tid = threadIdx.x;
    const int lane = tid & 31, w = tid >> 5;
    const int wm = w >> 2, wn = w & 3;
    const int g = lane >> 2, tg = lane & 3;
    const int b0 = blockIdx.x * 128;
    const int e  = blockIdx.y;

    const __half* W1e = g_W1T + (size_t)e * H_DIM * S_DIM;   // [256][64]
    const __half* W2e = g_W2T + (size_t)e * H_DIM * H_DIM;   // [256][256]

    auto loadW2 = [&](__half* buf, int kc) {   // 256 rows x 64 halves
        #pragma unroll
        for (int j = 0; j < 8; ++j) {
            int lin = j * 256 + tid, row = lin >> 3, seg = lin & 7;
            cp16(buf + row * 72 + seg * 8, W2e + (size_t)row * 256 + kc * 64 + seg * 8);
        }
    };

    // phase-1 loads: state 128x64 halves (8 units/row), W1T 256x64
    #pragma unroll
    for (int j = 0; j < 4; ++j) {
        int lin = j * 256 + tid, row = lin >> 3, seg = lin & 7;
        cp16(sS + row * 72 + seg * 8, g_Sh + (size_t)(b0 + row) * S_DIM + seg * 8);
    }
    #pragma unroll
    for (int j = 0; j < 8; ++j) {
        int lin = j * 256 + tid, row = lin >> 3, seg = lin & 7;
        cp16(sW1 + row * 72 + seg * 8, W1e + (size_t)row * S_DIM + seg * 8);
    }
    cp_commit();
    loadW2(sW2a, 0); cp_commit();
    loadW2(sW2b, 1); cp_commit();
    cp_wait<2>(); __syncthreads();

    // ---- layer 1: K=64 -> 4 ksteps of k16 ----
    float acc[4][8][4];
    #pragma unroll
    for (int t = 0; t < 4; ++t)
        #pragma unroll
        for (int u = 0; u < 8; ++u)
            #pragma unroll
            for (int v = 0; v < 4; ++v) acc[t][u][v] = 0.f;

    #pragma unroll
    for (int ks = 0; ks < 4; ++ks) {
        const int kw = ks * 8;   // word offset (k16 = 8 words)
        uint32_t a[4][4];
        #pragma unroll
        for (int t = 0; t < 4; ++t) {
            const uint32_t* ap = (const uint32_t*)sS + (wm * 64 + t * 16 + g) * 36 + kw + tg;
            a[t][0] = ap[0];
            a[t][1] = ap[8 * 36];
            a[t][2] = ap[4];
            a[t][3] = ap[8 * 36 + 4];
        }
        uint32_t b[8][2];
        #pragma unroll
        for (int u = 0; u < 8; ++u) {
            const uint32_t* bp = (const uint32_t*)sW1 + (wn * 64 + u * 8 + g) * 36 + kw + tg;
            b[u][0] = bp[0];
            b[u][1] = bp[4];
        }
        #pragma unroll
        for (int t = 0; t < 4; ++t)
            #pragma unroll
            for (int u = 0; u < 8; ++u)
                mma_f16(acc[t][u], a[t], b[u]);
    }
    __syncthreads();   // done reading sS / sW1

    // epilogue 1: tanh + bias -> sH (half2 stores)
    #pragma unroll
    for (int t = 0; t < 4; ++t) {
        int r = wm * 64 + t * 16 + g;
        #pragma unroll
        for (int u = 0; u < 8; ++u) {
            int cl = wn * 64 + u * 8 + tg * 2;
            float bb0 = b1[(size_t)e * H_DIM + cl];
            float bb1 = b1[(size_t)e * H_DIM + cl + 1];
            __half2 v0 = __floats2half2_rn(tanhf(acc[t][u][0] + bb0),
                                           tanhf(acc[t][u][1] + bb1));
            __half2 v1 = __floats2half2_rn(tanhf(acc[t][u][2] + bb0),
                                           tanhf(acc[t][u][3] + bb1));
            *(__half2*)(sH + r * 264 + cl)       = v0;
            *(__half2*)(sH + (r + 8) * 264 + cl) = v1;
        }
    }
    __syncthreads();

    // ---- layer 2: K=256 -> 4 chunks of 64 halves, 4 ksteps each ----
    #pragma unroll
    for (int t = 0; t < 4; ++t)
        #pragma unroll
        for (int u = 0; u < 8; ++u)
            #pragma unroll
            for (int v = 0; v < 4; ++v) acc[t][u][v] = 0.f;

    for (int kc = 0; kc < 4; ++kc) {
        if (kc < 3) cp_wait<1>(); else cp_wait<0>();
        __syncthreads();
        const __half* cB = (kc & 1) ? sW2b : sW2a;
        #pragma unroll
        for (int ks = 0; ks < 4; ++ks) {
            const int kwA = kc * 32 + ks * 8;   // word offset into sH row
            const int kwB = ks * 8;             // word offset into W2 chunk
            uint32_t a[4][4];
            #pragma unroll
            for (int t = 0; t < 4; ++t) {
                const uint32_t* ap = (const uint32_t*)sH + (wm * 64 + t * 16 + g) * 132 + kwA + tg;
                a[t][0] = ap[0];
                a[t][1] = ap[8 * 132];
                a[t][2] = ap[4];
                a[t][3] = ap[8 * 132 + 4];
            }
            uint32_t b[8][2];
            #pragma unroll
            for (int u = 0; u < 8; ++u) {
                const uint32_t* bp = (const uint32_t*)cB + (wn * 64 + u * 8 + g) * 36 + kwB + tg;
                b[u][0] = bp[0];
                b[u][1] = bp[4];
            }
            #pragma unroll
            for (int t = 0; t < 4; ++t)
                #pragma unroll
                for (int u = 0; u < 8; ++u)
                    mma_f16(acc[t][u], a[t], b[u]);
        }
        __syncthreads();
        if (kc + 2 < 4) {
            loadW2((kc & 1) ? sW2b : sW2a, kc + 2);
            cp_commit();
        }
    }

    // epilogue 2: tanh + bias -> g_H (half2)
    #pragma unroll
    for (int t = 0; t < 4; ++t) {
        size_t r = (size_t)b0 + wm * 64 + t * 16 + g;
        #pragma unroll
        for (int u = 0; u < 8; ++u) {
            int cl = wn * 64 + u * 8 + tg * 2;
            float bb0 = b2[(size_t)e * H_DIM + cl];
            float bb1 = b2[(size_t)e * H_DIM + cl + 1];
            __half2 v0 = __floats2half2_rn(tanhf(acc[t][u][0] + bb0),
                                           tanhf(acc[t][u][1] + bb1));
            __half2 v1 = __floats2half2_rn(tanhf(acc[t][u][2] + bb0),
                                           tanhf(acc[t][u][3] + bb1));
            __half* dst = g_H + r * K_CAT + e * H_DIM + cl;
            *(__half2*)dst = v0;
            *(__half2*)(dst + 8 * K_CAT) = v1;
        }
    }
}

// ---------------------------------------------------------------------------
// Pass 2: fp16 m16n8k16 GEMM. out[m][n] = 0.125*(sum_k H[m,k]*WT[n,k] + bs[n])
// CTA 128 x TN, 4 warps (2x2), warp 64 x TN/2. K chunks of 64 halves.
// ---------------------------------------------------------------------------
template<int TN>
__global__ void __launch_bounds__(128, 2) k_mma(
    const __half* __restrict__ WT, const float* __restrict__ bsum,
    float* __restrict__ out, int Ntot)
{
    constexpr int NT  = TN / 16;
    constexpr int NCH = K_CAT / 64;

    extern __shared__ __half smh[];
    __half* sA0 = smh;
    __half* sA1 = sA0 + 128 * 72;
    __half* sB0 = sA1 + 128 * 72;
    __half* sB1 = sB0 + TN * 72;
    float*  sBias = (float*)(sB1 + TN * 72);

    const int tid = threadIdx.x;
    const int lane = tid & 31, w = tid >> 5;
    const int wm = w >> 1, wn = w & 1;
    const int g = lane >> 2, tg = lane & 3;
    const int bm = blockIdx.x, bn = blockIdx.y;

    const __half* Abase = g_H + (size_t)bm * 128 * K_CAT;
    const __half* Bbase = WT + (size_t)bn * TN * K_CAT;

    if (tid < TN) sBias[tid] = bsum[(size_t)bn * TN + tid];

    auto loadA = [&](__half* buf, int kc) {   // 128 rows x 64 halves
        #pragma unroll
        for (int j = 0; j < 8; ++j) {
            int lin = j * 128 + tid, row = lin >> 3, seg = lin & 7;
            cp16(buf + row * 72 + seg * 8, Abase + (size_t)row * K_CAT + kc * 64 + seg * 8);
        }
    };
    auto loadB = [&](__half* buf, int kc) {   // TN rows x 64 halves
        #pragma unroll
        for (int j = 0; j < TN / 16; ++j) {
            int lin = j * 128 + tid, row = lin >> 3, seg = lin & 7;
            cp16(buf + row * 72 + seg * 8, Bbase + (size_t)row * K_CAT + kc * 64 + seg * 8);
        }
    };

    float acc[4][NT][4];
    #pragma unroll
    for (int t = 0; t < 4; ++t)
        #pragma unroll
        for (int u = 0; u < NT; ++u)
            #pragma unroll
            for (int v = 0; v < 4; ++v) acc[t][u][v] = 0.f;

    loadA(sA0, 0); loadB(sB0, 0); cp_commit();

    for (int kc = 0; kc < NCH; ++kc) {
        if (kc + 1 < NCH) {
            loadA((kc & 1) ? sA0 : sA1, kc + 1);
            loadB((kc & 1) ? sB0 : sB1, kc + 1);
            cp_commit(); cp_wait<1>();
        } else {
            cp_wait<0>();
        }
        __syncthreads();
        const __half* cA = (kc & 1) ? sA1 : sA0;
        const __half* cB = (kc & 1) ? sB1 : sB0;

        #pragma unroll
        for (int ks = 0; ks < 4; ++ks) {
            const int kw = ks * 8;
            uint32_t a[4][4];
            #pragma unroll
            for (int t = 0; t < 4; ++t) {
                const uint32_t* ap = (const uint32_t*)cA + (wm * 64 + t * 16 + g) * 36 + kw + tg;
                a[t][0] = ap[0];
                a[t][1] = ap[8 * 36];
                a[t][2] = ap[4];
                a[t][3] = ap[8 * 36 + 4];
            }
            uint32_t b[NT][2];
            #pragma unroll
            for (int u = 0; u < NT; ++u) {
                const uint32_t* bp = (const uint32_t*)cB + (wn * (TN / 2) + u * 8 + g) * 36 + kw + tg;
                b[u][0] = bp[0];
                b[u][1] = bp[4];
            }
            #pragma unroll
            for (int t = 0; t < 4; ++t)
                #pragma unroll
                for (int u = 0; u < NT; ++u)
                    mma_f16(acc[t][u], a[t], b[u]);
        }
        __syncthreads();
    }

    #pragma unroll
    for (int t = 0; t < 4; ++t) {
        size_t r0 = (size_t)bm * 128 + wm * 64 + t * 16 + g;
        #pragma unroll
        for (int u = 0; u < NT; ++u) {
            int cl = wn * (TN / 2) + u * 8 + tg * 2;
            size_t c = (size_t)bn * TN + cl;
            float bs0 = sBias[cl], bs1 = sBias[cl + 1];
            float2 v0, v1;
            v0.x = 0.125f * (acc[t][u][0] + bs0);
            v0.y = 0.125f * (acc[t][u][1] + bs1);
            v1.x = 0.125f * (acc[t][u][2] + bs0);
            v1.y = 0.125f * (acc[t][u][3] + bs1);
            *(float2*)(out + r0 * Ntot + c)       = v0;
            *(float2*)(out + (r0 + 8) * Ntot + c) = v1;
        }
    }
}

// ---------------------------------------------------------------------------
extern "C" void kernel_launch(void* const* d_in, const int* in_sizes, int n_in,
                              void* d_out, int out_size)
{
    const float* state = (const float*)d_in[0];
    const float* W1    = (const float*)d_in[1];
    const float* b1    = (const float*)d_in[2];
    const float* W2    = (const float*)d_in[3];
    const float* b2    = (const float*)d_in[4];
    const float* Wf    = (const float*)d_in[5];
    const float* bf    = (const float*)d_in[6];
    const float* Wg    = (const float*)d_in[7];
    const float* bg    = (const float*)d_in[8];

    float* out   = (float*)d_out;
    float* out_f = out;                              // f_mean [B, 64]
    float* out_g = out + (size_t)B_DIM * S_DIM;      // g_mean [B, 1024]

    __half* WgT; cudaGetSymbolAddress((void**)&WgT, g_WgT);
    __half* WfT; cudaGetSymbolAddress((void**)&WfT, g_WfT);
    __half* W1T; cudaGetSymbolAddress((void**)&W1T, g_W1T);
    __half* W2T; cudaGetSymbolAddress((void**)&W2T, g_W2T);
    float*  bsm; cudaGetSymbolAddress((void**)&bsm, g_bsum);

    const int smemM = (128 * 264 + 2 * 256 * 72) * 2;            // 141,312 B
    const int smemG = (2 * 128 * 72 + 2 * 128 * 72) * 2 + 512;   // 74,240 B
    const int smemF = (2 * 128 * 72 + 2 * 64 * 72) * 2 + 256;    // 55,552 B

    cudaFuncSetAttribute(k_mlp, cudaFuncAttributeMaxDynamicSharedMemorySize, smemM);
    cudaFuncSetAttribute(k_mma<128>, cudaFuncAttributeMaxDynamicSharedMemorySize, smemG);
    cudaFuncSetAttribute(k_mma<64>,  cudaFuncAttributeMaxDynamicSharedMemorySize, smemF);

    k_bias<<<(N_G + N_F + 255) / 256, 256>>>(bg, bf);
    k_cvt_state<<<(B_DIM * S_DIM / 4) / 256, 256>>>(state);
    k_trw<<<dim3(K_CAT / 32, N_G / 32, 1), dim3(32, 8)>>>(Wg, WgT, K_CAT, N_G);
    k_trw<<<dim3(K_CAT / 32, N_F / 32, 1), dim3(32, 8)>>>(Wf, WfT, K_CAT, N_F);
    k_trw<<<dim3(S_DIM / 32, H_DIM / 32, E_DIM), dim3(32, 8)>>>(W1, W1T, S_DIM, H_DIM);
    k_trw<<<dim3(H_DIM / 32, H_DIM / 32, E_DIM), dim3(32, 8)>>>(W2, W2T, H_DIM, H_DIM);

    k_mlp<<<dim3(B_DIM / 128, E_DIM), 256, smemM>>>(b1, b2);

    k_mma<128><<<dim3(B_DIM / 128, N_G / 128), 128, smemG>>>(WgT, bsm, out_g, N_G);
    k_mma<64><<<dim3(B_DIM / 128, 1), 128, smemF>>>(WfT, bsm + N_G, out_f, N_F);
}

// round 6
// speedup vs baseline: 5.9367x; 1.0222x over previous
#include <cuda_runtime.h>
#include <cuda_fp16.h>
#include <math.h>
#include <stdint.h>

#define B_DIM 16384
#define S_DIM 64
#define A_DIM 16
#define H_DIM 256
#define E_DIM 8
#define K_CAT 2048   // E * H
#define N_G   1024   // S*A
#define N_F   64

// scratch (all fp16 operands)
__device__ __half g_H[(size_t)B_DIM * K_CAT];            // Hcat, 67 MB
__device__ __half g_Sh[(size_t)B_DIM * S_DIM];           // state fp16
__device__ __half g_WgT[(size_t)N_G * K_CAT];            // Wg^T [n][k]
__device__ __half g_WfT[(size_t)N_F * K_CAT];            // Wf^T [n][k]
__device__ __half g_W1T[(size_t)E_DIM * H_DIM * S_DIM];  // [e][h][s]
__device__ __half g_W2T[(size_t)E_DIM * H_DIM * H_DIM];  // [e][hout][hin]
__device__ float  g_bsum[N_G + N_F];                     // sum_e bias (fp32)

// ---------------------------------------------------------------- helpers
__device__ __forceinline__ uint32_t s2u(const void* p) {
    return (uint32_t)__cvta_generic_to_shared(p);
}
__device__ __forceinline__ void cp16(void* dst, const void* src) {
    asm volatile("cp.async.cg.shared.global [%0], [%1], 16;"
                 :: "r"(s2u(dst)), "l"(src));
}
__device__ __forceinline__ void cp_commit() { asm volatile("cp.async.commit_group;"); }
template<int N> __device__ __forceinline__ void cp_wait() {
    asm volatile("cp.async.wait_group %0;" :: "n"(N));
}
__device__ __forceinline__ void ldsm4(uint32_t* r, uint32_t addr) {
    asm volatile("ldmatrix.sync.aligned.m8n8.x4.shared.b16 {%0,%1,%2,%3}, [%4];"
                 : "=r"(r[0]), "=r"(r[1]), "=r"(r[2]), "=r"(r[3]) : "r"(addr));
}
// m16n8k16 fp16 -> fp32 acc
__device__ __forceinline__ void mma_f16(float* d, const uint32_t* a, const uint32_t* b) {
    asm volatile(
        "mma.sync.aligned.m16n8k16.row.col.f32.f16.f16.f32 "
        "{%0,%1,%2,%3},{%4,%5,%6,%7},{%8,%9},{%0,%1,%2,%3};"
        : "+f"(d[0]), "+f"(d[1]), "+f"(d[2]), "+f"(d[3])
        : "r"(a[0]), "r"(a[1]), "r"(a[2]), "r"(a[3]), "r"(b[0]), "r"(b[1]));
}

// ---------------------------------------------------------------------------
// Prep kernels
// ---------------------------------------------------------------------------
__global__ void k_cvt_state(const float* __restrict__ s) {
    int i = blockIdx.x * 256 + threadIdx.x;
    float4 v = *(const float4*)(s + (size_t)i * 4);
    __half2 h0 = __floats2half2_rn(v.x, v.y);
    __half2 h1 = __floats2half2_rn(v.z, v.w);
    *(uint2*)(g_Sh + (size_t)i * 4) = make_uint2(*(uint32_t*)&h0, *(uint32_t*)&h1);
}

__global__ void k_trw(const float* __restrict__ W, __half* __restrict__ WT,
                      int K, int N) {
    __shared__ float t[32][33];
    const float* Wb = W + (size_t)blockIdx.z * K * N;
    __half* WTb = WT + (size_t)blockIdx.z * K * N;
    int k0 = blockIdx.x * 32, n0 = blockIdx.y * 32;
    int x = threadIdx.x, y = threadIdx.y;  // 32 x 8
    #pragma unroll
    for (int i = 0; i < 32; i += 8)
        t[y + i][x] = Wb[(size_t)(k0 + y + i) * N + n0 + x];
    __syncthreads();
    #pragma unroll
    for (int i = 0; i < 32; i += 8)
        WTb[(size_t)(n0 + y + i) * K + k0 + x] = __float2half_rn(t[x][y + i]);
}

__global__ void k_bias(const float* __restrict__ bg, const float* __restrict__ bf) {
    int q = blockIdx.x * 256 + threadIdx.x;
    if (q < N_G) {
        float s = 0.f;
        #pragma unroll
        for (int e = 0; e < E_DIM; ++e) s += bg[(size_t)e * N_G + q];
        g_bsum[q] = s;
    } else if (q < N_G + N_F) {
        int qq = q - N_G;
        float s = 0.f;
        #pragma unroll
        for (int e = 0; e < E_DIM; ++e) s += bf[(size_t)e * N_F + qq];
        g_bsum[q] = s;
    }
}

// ---------------------------------------------------------------------------
// Pass 1: CTA = (128 batch rows, member e). fp16 m16n8k16 MMA + ldmatrix.
// 8 warps (wm 0..1, wn 0..3), warp tile 64x64.
// SMEM half strides: 72 (state/W1/W2 chunks), 264 (h1).
// ---------------------------------------------------------------------------
__global__ void __launch_bounds__(256, 1) k_mlp(
    const float* __restrict__ b1, const float* __restrict__ b2)
{
    extern __shared__ __half smh[];
    __half* sS   = smh;                  // [128][72] phase 1
    __half* sW1  = smh + 128 * 72;       // [256][72] phase 1
    __half* sH   = smh;                  // [128][264] phase 2
    __half* sW2a = smh + 128 * 264;      // [256][72]
    __half* sW2b = sW2a + 256 * 72;

    const int tid = threadIdx.x;
    const int lane = tid & 31, w = tid >> 5;
    const int wm = w >> 2, wn = w & 3;
    const int g = lane >> 2, tg = lane & 3;
    const int mi = lane >> 3, ri = lane & 7;
    const int b0 = blockIdx.x * 128;
    const int e  = blockIdx.y;

    const __half* W1e = g_W1T + (size_t)e * H_DIM * S_DIM;
    const __half* W2e = g_W2T + (size_t)e * H_DIM * H_DIM;

    auto loadW2 = [&](__half* buf, int kc) {
        #pragma unroll
        for (int j = 0; j < 8; ++j) {
            int lin = j * 256 + tid, row = lin >> 3, seg = lin & 7;
            cp16(buf + row * 72 + seg * 8, W2e + (size_t)row * 256 + kc * 64 + seg * 8);
        }
    };

    #pragma unroll
    for (int j = 0; j < 4; ++j) {
        int lin = j * 256 + tid, row = lin >> 3, seg = lin & 7;
        cp16(sS + row * 72 + seg * 8, g_Sh + (size_t)(b0 + row) * S_DIM + seg * 8);
    }
    #pragma unroll
    for (int j = 0; j < 8; ++j) {
        int lin = j * 256 + tid, row = lin >> 3, seg = lin & 7;
        cp16(sW1 + row * 72 + seg * 8, W1e + (size_t)row * S_DIM + seg * 8);
    }
    cp_commit();
    loadW2(sW2a, 0); cp_commit();
    loadW2(sW2b, 1); cp_commit();
    cp_wait<2>(); __syncthreads();

    // fragment base addresses (bytes)
    const uint32_t uS  = s2u(sS),  uW1 = s2u(sW1);
    const uint32_t uH  = s2u(sH),  uW2 = s2u(sW2a);
    uint32_t aoff72[4], aoff264[4], boff72[4];
    #pragma unroll
    for (int t = 0; t < 4; ++t) {
        int rrow = wm * 64 + t * 16 + ri + (mi & 1) * 8;
        int kadd = (mi >> 1) * 8;
        aoff72[t]  = (uint32_t)(rrow * 72  + kadd) * 2;
        aoff264[t] = (uint32_t)(rrow * 264 + kadd) * 2;
    }
    #pragma unroll
    for (int j = 0; j < 4; ++j) {
        int nrow = wn * 64 + (j * 2 + (lane >> 4)) * 8 + ri;
        int kadd = ((lane >> 3) & 1) * 8;
        boff72[j] = (uint32_t)(nrow * 72 + kadd) * 2;
    }

    // ---- layer 1: K=64 -> 4 ksteps ----
    float acc[4][8][4];
    #pragma unroll
    for (int t = 0; t < 4; ++t)
        #pragma unroll
        for (int u = 0; u < 8; ++u)
            #pragma unroll
            for (int v = 0; v < 4; ++v) acc[t][u][v] = 0.f;

    #pragma unroll
    for (int ks = 0; ks < 4; ++ks) {
        uint32_t a[4][4], b[8][2];
        #pragma unroll
        for (int t = 0; t < 4; ++t) ldsm4(a[t], uS + aoff72[t] + ks * 32);
        #pragma unroll
        for (int j = 0; j < 4; ++j) {
            uint32_t r[4];
            ldsm4(r, uW1 + boff72[j] + ks * 32);
            b[2*j][0] = r[0]; b[2*j][1] = r[1];
            b[2*j+1][0] = r[2]; b[2*j+1][1] = r[3];
        }
        #pragma unroll
        for (int t = 0; t < 4; ++t)
            #pragma unroll
            for (int u = 0; u < 8; ++u)
                mma_f16(acc[t][u], a[t], b[u]);
    }
    __syncthreads();

    // epilogue 1: tanh + bias -> sH
    #pragma unroll
    for (int t = 0; t < 4; ++t) {
        int r = wm * 64 + t * 16 + g;
        #pragma unroll
        for (int u = 0; u < 8; ++u) {
            int cl = wn * 64 + u * 8 + tg * 2;
            float bb0 = b1[(size_t)e * H_DIM + cl];
            float bb1 = b1[(size_t)e * H_DIM + cl + 1];
            __half2 v0 = __floats2half2_rn(tanhf(acc[t][u][0] + bb0),
                                           tanhf(acc[t][u][1] + bb1));
            __half2 v1 = __floats2half2_rn(tanhf(acc[t][u][2] + bb0),
                                           tanhf(acc[t][u][3] + bb1));
            *(__half2*)(sH + r * 264 + cl)       = v0;
            *(__half2*)(sH + (r + 8) * 264 + cl) = v1;
        }
    }
    __syncthreads();

    // ---- layer 2: K=256 -> 4 chunks of 64 halves ----
    #pragma unroll
    for (int t = 0; t < 4; ++t)
        #pragma unroll
        for (int u = 0; u < 8; ++u)
            #pragma unroll
            for (int v = 0; v < 4; ++v) acc[t][u][v] = 0.f;

    for (int kc = 0; kc < 4; ++kc) {
        if (kc < 3) cp_wait<1>(); else cp_wait<0>();
        __syncthreads();
        const uint32_t stB = uW2 + (uint32_t)(kc & 1) * (256 * 72 * 2);
        #pragma unroll
        for (int ks = 0; ks < 4; ++ks) {
            const uint32_t kbyteA = (uint32_t)(kc * 64 + ks * 16) * 2;
            uint32_t a[4][4], b[8][2];
            #pragma unroll
            for (int t = 0; t < 4; ++t) ldsm4(a[t], uH + aoff264[t] + kbyteA);
            #pragma unroll
            for (int j = 0; j < 4; ++j) {
                uint32_t r[4];
                ldsm4(r, stB + boff72[j] + ks * 32);
                b[2*j][0] = r[0]; b[2*j][1] = r[1];
                b[2*j+1][0] = r[2]; b[2*j+1][1] = r[3];
            }
            #pragma unroll
            for (int t = 0; t < 4; ++t)
                #pragma unroll
                for (int u = 0; u < 8; ++u)
                    mma_f16(acc[t][u], a[t], b[u]);
        }
        __syncthreads();
        if (kc + 2 < 4) {
            loadW2((kc & 1) ? sW2b : sW2a, kc + 2);
            cp_commit();
        }
    }

    // epilogue 2: tanh + bias -> g_H
    #pragma unroll
    for (int t = 0; t < 4; ++t) {
        size_t r = (size_t)b0 + wm * 64 + t * 16 + g;
        #pragma unroll
        for (int u = 0; u < 8; ++u) {
            int cl = wn * 64 + u * 8 + tg * 2;
            float bb0 = b2[(size_t)e * H_DIM + cl];
            float bb1 = b2[(size_t)e * H_DIM + cl + 1];
            __half2 v0 = __floats2half2_rn(tanhf(acc[t][u][0] + bb0),
                                           tanhf(acc[t][u][1] + bb1));
            __half2 v1 = __floats2half2_rn(tanhf(acc[t][u][2] + bb0),
                                           tanhf(acc[t][u][3] + bb1));
            __half* dst = g_H + r * K_CAT + e * H_DIM + cl;
            *(__half2*)dst = v0;
            *(__half2*)(dst + 8 * K_CAT) = v1;
        }
    }
}

// ---------------------------------------------------------------------------
// Pass 2: fp16 m16n8k16 GEMM + ldmatrix.
// out[m][n] = 0.125*(sum_k H[m,k]*WT[n,k] + bs[n])
// CTA 128 x TN, 4 warps (2x2), warp 64 x TN/2. K chunks of 64 halves.
// ---------------------------------------------------------------------------
template<int TN>
__global__ void __launch_bounds__(128, 2) k_mma(
    const __half* __restrict__ WT, const float* __restrict__ bsum,
    float* __restrict__ out, int Ntot)
{
    constexpr int NT  = TN / 16;
    constexpr int NCH = K_CAT / 64;
    constexpr uint32_t ASTG = 128 * 72 * 2;   // A stage bytes
    constexpr uint32_t BSTG = TN * 72 * 2;    // B stage bytes

    extern __shared__ __half smh[];
    __half* sA0 = smh;
    __half* sB0 = smh + 2 * 128 * 72;
    float*  sBias = (float*)(sB0 + 2 * TN * 72);

    const int tid = threadIdx.x;
    const int lane = tid & 31, w = tid >> 5;
    const int wm = w >> 1, wn = w & 1;
    const int g = lane >> 2, tg = lane & 3;
    const int mi = lane >> 3, ri = lane & 7;
    const int bm = blockIdx.x, bn = blockIdx.y;

    const __half* Abase = g_H + (size_t)bm * 128 * K_CAT;
    const __half* Bbase = WT + (size_t)bn * TN * K_CAT;

    if (tid < TN) sBias[tid] = bsum[(size_t)bn * TN + tid];

    auto loadA = [&](int stage, int kc) {
        __half* buf = sA0 + stage * (128 * 72);
        #pragma unroll
        for (int j = 0; j < 8; ++j) {
            int lin = j * 128 + tid, row = lin >> 3, seg = lin & 7;
            cp16(buf + row * 72 + seg * 8, Abase + (size_t)row * K_CAT + kc * 64 + seg * 8);
        }
    };
    auto loadB = [&](int stage, int kc) {
        __half* buf = sB0 + stage * (TN * 72);
        #pragma unroll
        for (int j = 0; j < TN / 16; ++j) {
            int lin = j * 128 + tid, row = lin >> 3, seg = lin & 7;
            cp16(buf + row * 72 + seg * 8, Bbase + (size_t)row * K_CAT + kc * 64 + seg * 8);
        }
    };

    const uint32_t uA = s2u(sA0), uB = s2u(sB0);
    uint32_t aoff[4], boff[NT / 2];
    #pragma unroll
    for (int t = 0; t < 4; ++t)
        aoff[t] = (uint32_t)((wm * 64 + t * 16 + ri + (mi & 1) * 8) * 72 +
                             (mi >> 1) * 8) * 2;
    #pragma unroll
    for (int j = 0; j < NT / 2; ++j)
        boff[j] = (uint32_t)((wn * (TN / 2) + (j * 2 + (lane >> 4)) * 8 + ri) * 72 +
                             ((lane >> 3) & 1) * 8) * 2;

    float acc[4][NT][4];
    #pragma unroll
    for (int t = 0; t < 4; ++t)
        #pragma unroll
        for (int u = 0; u < NT; ++u)
            #pragma unroll
            for (int v = 0; v < 4; ++v) acc[t][u][v] = 0.f;

    loadA(0, 0); loadB(0, 0); cp_commit();

    for (int kc = 0; kc < NCH; ++kc) {
        if (kc + 1 < NCH) {
            loadA((kc + 1) & 1, kc + 1);
            loadB((kc + 1) & 1, kc + 1);
            cp_commit(); cp_wait<1>();
        } else {
            cp_wait<0>();
        }
        __syncthreads();
        const uint32_t stA = uA + (uint32_t)(kc & 1) * ASTG;
        const uint32_t stB = uB + (uint32_t)(kc & 1) * BSTG;

        #pragma unroll
        for (int ks = 0; ks < 4; ++ks) {
            uint32_t a[4][4], b[NT][2];
            #pragma unroll
            for (int t = 0; t < 4; ++t) ldsm4(a[t], stA + aoff[t] + ks * 32);
            #pragma unroll
            for (int j = 0; j < NT / 2; ++j) {
                uint32_t r[4];
                ldsm4(r, stB + boff[j] + ks * 32);
                b[2*j][0] = r[0]; b[2*j][1] = r[1];
                b[2*j+1][0] = r[2]; b[2*j+1][1] = r[3];
            }
            #pragma unroll
            for (int t = 0; t < 4; ++t)
                #pragma unroll
                for (int u = 0; u < NT; ++u)
                    mma_f16(acc[t][u], a[t], b[u]);
        }
        __syncthreads();
    }

    #pragma unroll
    for (int t = 0; t < 4; ++t) {
        size_t r0 = (size_t)bm * 128 + wm * 64 + t * 16 + g;
        #pragma unroll
        for (int u = 0; u < NT; ++u) {
            int cl = wn * (TN / 2) + u * 8 + tg * 2;
            size_t c = (size_t)bn * TN + cl;
            float bs0 = sBias[cl], bs1 = sBias[cl + 1];
            float2 v0, v1;
            v0.x = 0.125f * (acc[t][u][0] + bs0);
            v0.y = 0.125f * (acc[t][u][1] + bs1);
            v1.x = 0.125f * (acc[t][u][2] + bs0);
            v1.y = 0.125f * (acc[t][u][3] + bs1);
            *(float2*)(out + r0 * Ntot + c)       = v0;
            *(float2*)(out + (r0 + 8) * Ntot + c) = v1;
        }
    }
}

// ---------------------------------------------------------------------------
extern "C" void kernel_launch(void* const* d_in, const int* in_sizes, int n_in,
                              void* d_out, int out_size)
{
    const float* state = (const float*)d_in[0];
    const float* W1    = (const float*)d_in[1];
    const float* b1    = (const float*)d_in[2];
    const float* W2    = (const float*)d_in[3];
    const float* b2    = (const float*)d_in[4];
    const float* Wf    = (const float*)d_in[5];
    const float* bf    = (const float*)d_in[6];
    const float* Wg    = (const float*)d_in[7];
    const float* bg    = (const float*)d_in[8];

    float* out   = (float*)d_out;
    float* out_f = out;                              // f_mean [B, 64]
    float* out_g = out + (size_t)B_DIM * S_DIM;      // g_mean [B, 1024]

    __half* WgT; cudaGetSymbolAddress((void**)&WgT, g_WgT);
    __half* WfT; cudaGetSymbolAddress((void**)&WfT, g_WfT);
    __half* W1T; cudaGetSymbolAddress((void**)&W1T, g_W1T);
    __half* W2T; cudaGetSymbolAddress((void**)&W2T, g_W2T);
    float*  bsm; cudaGetSymbolAddress((void**)&bsm, g_bsum);

    const int smemM = (128 * 264 + 2 * 256 * 72) * 2;            // 141,312 B
    const int smemG = (2 * 128 * 72 + 2 * 128 * 72) * 2 + 512;   // 74,240 B
    const int smemF = (2 * 128 * 72 + 2 * 64 * 72) * 2 + 256;    // 55,552 B

    cudaFuncSetAttribute(k_mlp, cudaFuncAttributeMaxDynamicSharedMemorySize, smemM);
    cudaFuncSetAttribute(k_mma<128>, cudaFuncAttributeMaxDynamicSharedMemorySize, smemG);
    cudaFuncSetAttribute(k_mma<64>,  cudaFuncAttributeMaxDynamicSharedMemorySize, smemF);

    k_bias<<<(N_G + N_F + 255) / 256, 256>>>(bg, bf);
    k_cvt_state<<<(B_DIM * S_DIM / 4) / 256, 256>>>(state);
    k_trw<<<dim3(K_CAT / 32, N_G / 32, 1), dim3(32, 8)>>>(Wg, WgT, K_CAT, N_G);
    k_trw<<<dim3(K_CAT / 32, N_F / 32, 1), dim3(32, 8)>>>(Wf, WfT, K_CAT, N_F);
    k_trw<<<dim3(S_DIM / 32, H_DIM / 32, E_DIM), dim3(32, 8)>>>(W1, W1T, S_DIM, H_DIM);
    k_trw<<<dim3(H_DIM / 32, H_DIM / 32, E_DIM), dim3(32, 8)>>>(W2, W2T, H_DIM, H_DIM);

    k_mlp<<<dim3(B_DIM / 128, E_DIM), 256, smemM>>>(b1, b2);

    k_mma<128><<<dim3(B_DIM / 128, N_G / 128), 128, smemG>>>(WgT, bsm, out_g, N_G);
    k_mma<64><<<dim3(B_DIM / 128, 1), 128, smemF>>>(WfT, bsm + N_G, out_f, N_F);
}

// round 7
// speedup vs baseline: 6.5103x; 1.0966x over previous
#include <cuda_runtime.h>
#include <cuda_fp16.h>
#include <math.h>
#include <stdint.h>

#define B_DIM 16384
#define S_DIM 64
#define A_DIM 16
#define H_DIM 256
#define E_DIM 8
#define K_CAT 2048   // E * H
#define N_G   1024   // S*A
#define N_F   64

// scratch (all fp16 operands)
__device__ __half g_H[(size_t)B_DIM * K_CAT];            // Hcat, 67 MB
__device__ __half g_Sh[(size_t)B_DIM * S_DIM];           // state fp16
__device__ __half g_WgT[(size_t)N_G * K_CAT];            // Wg^T [n][k]
__device__ __half g_WfT[(size_t)N_F * K_CAT];            // Wf^T [n][k]
__device__ __half g_W1T[(size_t)E_DIM * H_DIM * S_DIM];  // [e][h][s]
__device__ __half g_W2T[(size_t)E_DIM * H_DIM * H_DIM];  // [e][hout][hin]
__device__ float  g_bsum[N_G + N_F];                     // sum_e bias (fp32)

// ---------------------------------------------------------------- helpers
__device__ __forceinline__ uint32_t s2u(const void* p) {
    return (uint32_t)__cvta_generic_to_shared(p);
}
__device__ __forceinline__ void cp16(void* dst, const void* src) {
    asm volatile("cp.async.cg.shared.global [%0], [%1], 16;"
                 :: "r"(s2u(dst)), "l"(src));
}
__device__ __forceinline__ void cp_commit() { asm volatile("cp.async.commit_group;"); }
template<int N> __device__ __forceinline__ void cp_wait() {
    asm volatile("cp.async.wait_group %0;" :: "n"(N));
}
__device__ __forceinline__ void ldsm4(uint32_t* r, uint32_t addr) {
    asm volatile("ldmatrix.sync.aligned.m8n8.x4.shared.b16 {%0,%1,%2,%3}, [%4];"
                 : "=r"(r[0]), "=r"(r[1]), "=r"(r[2]), "=r"(r[3]) : "r"(addr));
}
__device__ __forceinline__ void mma_f16(float* d, const uint32_t* a, const uint32_t* b) {
    asm volatile(
        "mma.sync.aligned.m16n8k16.row.col.f32.f16.f16.f32 "
        "{%0,%1,%2,%3},{%4,%5,%6,%7},{%8,%9},{%0,%1,%2,%3};"
        : "+f"(d[0]), "+f"(d[1]), "+f"(d[2]), "+f"(d[3])
        : "r"(a[0]), "r"(a[1]), "r"(a[2]), "r"(a[3]), "r"(b[0]), "r"(b[1]));
}

// ---------------------------------------------------------------------------
// Consolidated prep: all weight transposes + state cvt + bias sums, 1 launch.
// Blocks 0..2047:    Wg  [2048,1024] -> WgT
// Blocks 2048..2175: Wf  [2048,64]   -> WfT
// Blocks 2176..2303: W1  per-e [64,256]  -> W1T
// Blocks 2304..2815: W2  per-e [256,256] -> W2T
// Blocks 2816..3839: state f32 -> f16
// Blocks 3840..3844: bias sums
// ---------------------------------------------------------------------------
__device__ __forceinline__ void tr_tile(const float* __restrict__ W,
                                        __half* __restrict__ WT,
                                        int K, int N, int kt, int nt, int tid) {
    __shared__ float t[32][33];
    int x = tid & 31, y = tid >> 5;   // 32 x 8
    int k0 = kt * 32, n0 = nt * 32;
    #pragma unroll
    for (int i = 0; i < 32; i += 8)
        t[y + i][x] = W[(size_t)(k0 + y + i) * N + n0 + x];
    __syncthreads();
    #pragma unroll
    for (int i = 0; i < 32; i += 8)
        WT[(size_t)(n0 + y + i) * K + k0 + x] = __float2half_rn(t[x][y + i]);
}

__global__ void __launch_bounds__(256) k_prep(
    const float* __restrict__ state,
    const float* __restrict__ W1, const float* __restrict__ W2,
    const float* __restrict__ Wf, const float* __restrict__ Wg,
    const float* __restrict__ bg, const float* __restrict__ bf)
{
    const int id = blockIdx.x, tid = threadIdx.x;
    if (id < 2048) {
        tr_tile(Wg, g_WgT, K_CAT, N_G, id & 63, id >> 6, tid);
    } else if (id < 2176) {
        int t = id - 2048;
        tr_tile(Wf, g_WfT, K_CAT, N_F, t & 63, t >> 6, tid);
    } else if (id < 2304) {
        int t = id - 2176;
        int e = t >> 4; t &= 15;
        tr_tile(W1 + (size_t)e * S_DIM * H_DIM,
                g_W1T + (size_t)e * S_DIM * H_DIM,
                S_DIM, H_DIM, t & 1, t >> 1, tid);
    } else if (id < 2816) {
        int t = id - 2304;
        int e = t >> 6; t &= 63;
        tr_tile(W2 + (size_t)e * H_DIM * H_DIM,
                g_W2T + (size_t)e * H_DIM * H_DIM,
                H_DIM, H_DIM, t & 7, t >> 3, tid);
    } else if (id < 3840) {
        size_t i = ((size_t)(id - 2816) * 256 + tid) * 4;
        float4 v = *(const float4*)(state + i);
        __half2 h0 = __floats2half2_rn(v.x, v.y);
        __half2 h1 = __floats2half2_rn(v.z, v.w);
        *(uint2*)(g_Sh + i) = make_uint2(*(uint32_t*)&h0, *(uint32_t*)&h1);
    } else {
        int q = (id - 3840) * 256 + tid;
        if (q < N_G) {
            float s = 0.f;
            #pragma unroll
            for (int e = 0; e < E_DIM; ++e) s += bg[(size_t)e * N_G + q];
            g_bsum[q] = s;
        } else if (q < N_G + N_F) {
            int qq = q - N_G;
            float s = 0.f;
            #pragma unroll
            for (int e = 0; e < E_DIM; ++e) s += bf[(size_t)e * N_F + qq];
            g_bsum[q] = s;
        }
    }
}

// ---------------------------------------------------------------------------
// Pass 1: CTA = (128 batch rows, member e). fp16 m16n8k16 MMA + ldmatrix.
// (unchanged from round 6)
// ---------------------------------------------------------------------------
__global__ void __launch_bounds__(256, 1) k_mlp(
    const float* __restrict__ b1, const float* __restrict__ b2)
{
    extern __shared__ __half smh[];
    __half* sS   = smh;                  // [128][72] phase 1
    __half* sW1  = smh + 128 * 72;       // [256][72] phase 1
    __half* sH   = smh;                  // [128][264] phase 2
    __half* sW2a = smh + 128 * 264;      // [256][72]
    __half* sW2b = sW2a + 256 * 72;

    const int tid = threadIdx.x;
    const int lane = tid & 31, w = tid >> 5;
    const int wm = w >> 2, wn = w & 3;
    const int g = lane >> 2, tg = lane & 3;
    const int mi = lane >> 3, ri = lane & 7;
    const int b0 = blockIdx.x * 128;
    const int e  = blockIdx.y;

    const __half* W1e = g_W1T + (size_t)e * H_DIM * S_DIM;
    const __half* W2e = g_W2T + (size_t)e * H_DIM * H_DIM;

    auto loadW2 = [&](__half* buf, int kc) {
        #pragma unroll
        for (int j = 0; j < 8; ++j) {
            int lin = j * 256 + tid, row = lin >> 3, seg = lin & 7;
            cp16(buf + row * 72 + seg * 8, W2e + (size_t)row * 256 + kc * 64 + seg * 8);
        }
    };

    #pragma unroll
    for (int j = 0; j < 4; ++j) {
        int lin = j * 256 + tid, row = lin >> 3, seg = lin & 7;
        cp16(sS + row * 72 + seg * 8, g_Sh + (size_t)(b0 + row) * S_DIM + seg * 8);
    }
    #pragma unroll
    for (int j = 0; j < 8; ++j) {
        int lin = j * 256 + tid, row = lin >> 3, seg = lin & 7;
        cp16(sW1 + row * 72 + seg * 8, W1e + (size_t)row * S_DIM + seg * 8);
    }
    cp_commit();
    loadW2(sW2a, 0); cp_commit();
    loadW2(sW2b, 1); cp_commit();
    cp_wait<2>(); __syncthreads();

    const uint32_t uS  = s2u(sS),  uW1 = s2u(sW1);
    const uint32_t uH  = s2u(sH),  uW2 = s2u(sW2a);
    uint32_t aoff72[4], aoff264[4], boff72[4];
    #pragma unroll
    for (int t = 0; t < 4; ++t) {
        int rrow = wm * 64 + t * 16 + ri + (mi & 1) * 8;
        int kadd = (mi >> 1) * 8;
        aoff72[t]  = (uint32_t)(rrow * 72  + kadd) * 2;
        aoff264[t] = (uint32_t)(rrow * 264 + kadd) * 2;
    }
    #pragma unroll
    for (int j = 0; j < 4; ++j) {
        int nrow = wn * 64 + (j * 2 + (lane >> 4)) * 8 + ri;
        int kadd = ((lane >> 3) & 1) * 8;
        boff72[j] = (uint32_t)(nrow * 72 + kadd) * 2;
    }

    float acc[4][8][4];
    #pragma unroll
    for (int t = 0; t < 4; ++t)
        #pragma unroll
        for (int u = 0; u < 8; ++u)
            #pragma unroll
            for (int v = 0; v < 4; ++v) acc[t][u][v] = 0.f;

    #pragma unroll
    for (int ks = 0; ks < 4; ++ks) {
        uint32_t a[4][4], b[8][2];
        #pragma unroll
        for (int t = 0; t < 4; ++t) ldsm4(a[t], uS + aoff72[t] + ks * 32);
        #pragma unroll
        for (int j = 0; j < 4; ++j) {
            uint32_t r[4];
            ldsm4(r, uW1 + boff72[j] + ks * 32);
            b[2*j][0] = r[0]; b[2*j][1] = r[1];
            b[2*j+1][0] = r[2]; b[2*j+1][1] = r[3];
        }
        #pragma unroll
        for (int t = 0; t < 4; ++t)
            #pragma unroll
            for (int u = 0; u < 8; ++u)
                mma_f16(acc[t][u], a[t], b[u]);
    }
    __syncthreads();

    #pragma unroll
    for (int t = 0; t < 4; ++t) {
        int r = wm * 64 + t * 16 + g;
        #pragma unroll
        for (int u = 0; u < 8; ++u) {
            int cl = wn * 64 + u * 8 + tg * 2;
            float bb0 = b1[(size_t)e * H_DIM + cl];
            float bb1 = b1[(size_t)e * H_DIM + cl + 1];
            __half2 v0 = __floats2half2_rn(tanhf(acc[t][u][0] + bb0),
                                           tanhf(acc[t][u][1] + bb1));
            __half2 v1 = __floats2half2_rn(tanhf(acc[t][u][2] + bb0),
                                           tanhf(acc[t][u][3] + bb1));
            *(__half2*)(sH + r * 264 + cl)       = v0;
            *(__half2*)(sH + (r + 8) * 264 + cl) = v1;
        }
    }
    __syncthreads();

    #pragma unroll
    for (int t = 0; t < 4; ++t)
        #pragma unroll
        for (int u = 0; u < 8; ++u)
            #pragma unroll
            for (int v = 0; v < 4; ++v) acc[t][u][v] = 0.f;

    for (int kc = 0; kc < 4; ++kc) {
        if (kc < 3) cp_wait<1>(); else cp_wait<0>();
        __syncthreads();
        const uint32_t stB = uW2 + (uint32_t)(kc & 1) * (256 * 72 * 2);
        #pragma unroll
        for (int ks = 0; ks < 4; ++ks) {
            const uint32_t kbyteA = (uint32_t)(kc * 64 + ks * 16) * 2;
            uint32_t a[4][4], b[8][2];
            #pragma unroll
            for (int t = 0; t < 4; ++t) ldsm4(a[t], uH + aoff264[t] + kbyteA);
            #pragma unroll
            for (int j = 0; j < 4; ++j) {
                uint32_t r[4];
                ldsm4(r, stB + boff72[j] + ks * 32);
                b[2*j][0] = r[0]; b[2*j][1] = r[1];
                b[2*j+1][0] = r[2]; b[2*j+1][1] = r[3];
            }
            #pragma unroll
            for (int t = 0; t < 4; ++t)
                #pragma unroll
                for (int u = 0; u < 8; ++u)
                    mma_f16(acc[t][u], a[t], b[u]);
        }
        __syncthreads();
        if (kc + 2 < 4) {
            loadW2((kc & 1) ? sW2b : sW2a, kc + 2);
            cp_commit();
        }
    }

    #pragma unroll
    for (int t = 0; t < 4; ++t) {
        size_t r = (size_t)b0 + wm * 64 + t * 16 + g;
        #pragma unroll
        for (int u = 0; u < 8; ++u) {
            int cl = wn * 64 + u * 8 + tg * 2;
            float bb0 = b2[(size_t)e * H_DIM + cl];
            float bb1 = b2[(size_t)e * H_DIM + cl + 1];
            __half2 v0 = __floats2half2_rn(tanhf(acc[t][u][0] + bb0),
                                           tanhf(acc[t][u][1] + bb1));
            __half2 v1 = __floats2half2_rn(tanhf(acc[t][u][2] + bb0),
                                           tanhf(acc[t][u][3] + bb1));
            __half* dst = g_H + r * K_CAT + e * H_DIM + cl;
            *(__half2*)dst = v0;
            *(__half2*)(dst + 8 * K_CAT) = v1;
        }
    }
}

// ---------------------------------------------------------------------------
// Pass 2 tile worker: 128 x (NT*16) output tile, 3-stage cp.async pipeline,
// ONE __syncthreads per K-chunk.
// ---------------------------------------------------------------------------
template<int NT>
__device__ __forceinline__ void gemm_tile(
    const __half* __restrict__ Abase, const __half* __restrict__ Bbase,
    const float* __restrict__ bsumN, float* __restrict__ outBase, int Ntot,
    __half* smh, int tid)
{
    constexpr int TN  = NT * 16;
    constexpr int NCH = K_CAT / 64;

    __half* sA = smh;                    // 3 stages x 128 x 72
    __half* sB = smh + 3 * 128 * 72;     // 3 stages x TN x 72
    float*  sBias = (float*)(sB + 3 * TN * 72);

    const int lane = tid & 31, w = tid >> 5;
    const int wm = w >> 1, wn = w & 1;
    const int g = lane >> 2, tg = lane & 3;
    const int mi = lane >> 3, ri = lane & 7;

    if (tid < TN) sBias[tid] = bsumN[tid];

    auto loadA = [&](int stage, int kc) {
        __half* buf = sA + stage * (128 * 72);
        #pragma unroll
        for (int j = 0; j < 8; ++j) {
            int lin = j * 128 + tid, row = lin >> 3, seg = lin & 7;
            cp16(buf + row * 72 + seg * 8, Abase + (size_t)row * K_CAT + kc * 64 + seg * 8);
        }
    };
    auto loadB = [&](int stage, int kc) {
        __half* buf = sB + stage * (TN * 72);
        #pragma unroll
        for (int j = 0; j < TN / 16; ++j) {
            int lin = j * 128 + tid, row = lin >> 3, seg = lin & 7;
            cp16(buf + row * 72 + seg * 8, Bbase + (size_t)row * K_CAT + kc * 64 + seg * 8);
        }
    };

    const uint32_t uA = s2u(sA), uB = s2u(sB);
    uint32_t aoff[4], boff[NT / 2];
    #pragma unroll
    for (int t = 0; t < 4; ++t)
        aoff[t] = (uint32_t)((wm * 64 + t * 16 + ri + (mi & 1) * 8) * 72 +
                             (mi >> 1) * 8) * 2;
    #pragma unroll
    for (int j = 0; j < NT / 2; ++j)
        boff[j] = (uint32_t)((wn * (TN / 2) + (j * 2 + (lane >> 4)) * 8 + ri) * 72 +
                             ((lane >> 3) & 1) * 8) * 2;

    float acc[4][NT][4];
    #pragma unroll
    for (int t = 0; t < 4; ++t)
        #pragma unroll
        for (int u = 0; u < NT; ++u)
            #pragma unroll
            for (int v = 0; v < 4; ++v) acc[t][u][v] = 0.f;

    loadA(0, 0); loadB(0, 0); cp_commit();
    loadA(1, 1); loadB(1, 1); cp_commit();

    for (int kc = 0; kc < NCH; ++kc) {
        if (kc + 1 < NCH) cp_wait<1>(); else cp_wait<0>();
        __syncthreads();
        if (kc + 2 < NCH) {
            loadA((kc + 2) % 3, kc + 2);
            loadB((kc + 2) % 3, kc + 2);
            cp_commit();
        }
        const int stage = kc % 3;
        const uint32_t stA = uA + (uint32_t)stage * (128 * 72 * 2);
        const uint32_t stB = uB + (uint32_t)stage * (TN * 72 * 2);

        #pragma unroll
        for (int ks = 0; ks < 4; ++ks) {
            uint32_t a[4][4], b[NT][2];
            #pragma unroll
            for (int t = 0; t < 4; ++t) ldsm4(a[t], stA + aoff[t] + ks * 32);
            #pragma unroll
            for (int j = 0; j < NT / 2; ++j) {
                uint32_t r[4];
                ldsm4(r, stB + boff[j] + ks * 32);
                b[2*j][0] = r[0]; b[2*j][1] = r[1];
                b[2*j+1][0] = r[2]; b[2*j+1][1] = r[3];
            }
            #pragma unroll
            for (int t = 0; t < 4; ++t)
                #pragma unroll
                for (int u = 0; u < NT; ++u)
                    mma_f16(acc[t][u], a[t], b[u]);
        }
    }

    #pragma unroll
    for (int t = 0; t < 4; ++t) {
        size_t r0 = wm * 64 + t * 16 + g;
        #pragma unroll
        for (int u = 0; u < NT; ++u) {
            int cl = wn * (TN / 2) + u * 8 + tg * 2;
            float bs0 = sBias[cl], bs1 = sBias[cl + 1];
            float2 v0, v1;
            v0.x = 0.125f * (acc[t][u][0] + bs0);
            v0.y = 0.125f * (acc[t][u][1] + bs1);
            v1.x = 0.125f * (acc[t][u][2] + bs0);
            v1.y = 0.125f * (acc[t][u][3] + bs1);
            *(float2*)(outBase + r0 * Ntot + cl)       = v0;
            *(float2*)(outBase + (r0 + 8) * Ntot + cl) = v1;
        }
    }
}

// Merged output GEMM: blocks 0..1023 = g tiles (bm 0..127 x bn 0..7, TN=128),
// blocks 1024..1151 = f tiles (bm 0..127, TN=64).
__global__ void __launch_bounds__(128, 2) k_out(
    float* __restrict__ out_f, float* __restrict__ out_g)
{
    extern __shared__ __half smh[];
    const int id = blockIdx.x, tid = threadIdx.x;
    if (id < 1024) {
        const int bm = id & 127, bn = id >> 7;
        gemm_tile<8>(g_H + (size_t)bm * 128 * K_CAT,
                     g_WgT + (size_t)bn * 128 * K_CAT,
                     g_bsum + bn * 128,
                     out_g + (size_t)bm * 128 * N_G + bn * 128,
                     N_G, smh, tid);
    } else {
        const int bm = id - 1024;
        gemm_tile<4>(g_H + (size_t)bm * 128 * K_CAT,
                     g_WfT,
                     g_bsum + N_G,
                     out_f + (size_t)bm * 128 * N_F,
                     N_F, smh, tid);
    }
}

// ---------------------------------------------------------------------------
extern "C" void kernel_launch(void* const* d_in, const int* in_sizes, int n_in,
                              void* d_out, int out_size)
{
    const float* state = (const float*)d_in[0];
    const float* W1    = (const float*)d_in[1];
    const float* b1    = (const float*)d_in[2];
    const float* W2    = (const float*)d_in[3];
    const float* b2    = (const float*)d_in[4];
    const float* Wf    = (const float*)d_in[5];
    const float* bf    = (const float*)d_in[6];
    const float* Wg    = (const float*)d_in[7];
    const float* bg    = (const float*)d_in[8];

    float* out   = (float*)d_out;
    float* out_f = out;                              // f_mean [B, 64]
    float* out_g = out + (size_t)B_DIM * S_DIM;      // g_mean [B, 1024]

    const int smemM = (128 * 264 + 2 * 256 * 72) * 2;          // 141,312 B
    const int smemO = (3 * 128 * 72 + 3 * 128 * 72) * 2 + 512; // 111,104 B

    cudaFuncSetAttribute(k_mlp, cudaFuncAttributeMaxDynamicSharedMemorySize, smemM);
    cudaFuncSetAttribute(k_out, cudaFuncAttributeMaxDynamicSharedMemorySize, smemO);

    k_prep<<<3845, 256>>>(state, W1, W2, Wf, Wg, bg, bf);
    k_mlp<<<dim3(B_DIM / 128, E_DIM), 256, smemM>>>(b1, b2);
    k_out<<<1152, 128, smemO>>>(out_f, out_g);
}

// round 8
// speedup vs baseline: 6.5287x; 1.0028x over previous
#include <cuda_runtime.h>
#include <cuda_fp16.h>
#include <math.h>
#include <stdint.h>

#define B_DIM 16384
#define S_DIM 64
#define A_DIM 16
#define H_DIM 256
#define E_DIM 8
#define K_CAT 2048   // E * H
#define N_G   1024   // S*A
#define N_F   64

// scratch (all fp16 operands)
__device__ __half g_H[(size_t)B_DIM * K_CAT];            // Hcat, 67 MB
__device__ __half g_Sh[(size_t)B_DIM * S_DIM];           // state fp16
__device__ __half g_WgT[(size_t)N_G * K_CAT];            // Wg^T [n][k]
__device__ __half g_WfT[(size_t)N_F * K_CAT];            // Wf^T [n][k]
__device__ __half g_W1T[(size_t)E_DIM * H_DIM * S_DIM];  // [e][h][s]
__device__ __half g_W2T[(size_t)E_DIM * H_DIM * H_DIM];  // [e][hout][hin]
__device__ float  g_bsum[N_G + N_F];                     // sum_e bias (fp32)

// ---------------------------------------------------------------- helpers
__device__ __forceinline__ uint32_t s2u(const void* p) {
    return (uint32_t)__cvta_generic_to_shared(p);
}
__device__ __forceinline__ void cp16(void* dst, const void* src) {
    asm volatile("cp.async.cg.shared.global [%0], [%1], 16;"
                 :: "r"(s2u(dst)), "l"(src));
}
__device__ __forceinline__ void cp_commit() { asm volatile("cp.async.commit_group;"); }
template<int N> __device__ __forceinline__ void cp_wait() {
    asm volatile("cp.async.wait_group %0;" :: "n"(N));
}
__device__ __forceinline__ void ldsm4(uint32_t* r, uint32_t addr) {
    asm volatile("ldmatrix.sync.aligned.m8n8.x4.shared.b16 {%0,%1,%2,%3}, [%4];"
                 : "=r"(r[0]), "=r"(r[1]), "=r"(r[2]), "=r"(r[3]) : "r"(addr));
}
__device__ __forceinline__ void mma_f16(float* d, const uint32_t* a, const uint32_t* b) {
    asm volatile(
        "mma.sync.aligned.m16n8k16.row.col.f32.f16.f16.f32 "
        "{%0,%1,%2,%3},{%4,%5,%6,%7},{%8,%9},{%0,%1,%2,%3};"
        : "+f"(d[0]), "+f"(d[1]), "+f"(d[2]), "+f"(d[3])
        : "r"(a[0]), "r"(a[1]), "r"(a[2]), "r"(a[3]), "r"(b[0]), "r"(b[1]));
}

// ---------------------------------------------------------------------------
// Consolidated prep (unchanged)
// ---------------------------------------------------------------------------
__device__ __forceinline__ void tr_tile(const float* __restrict__ W,
                                        __half* __restrict__ WT,
                                        int K, int N, int kt, int nt, int tid) {
    __shared__ float t[32][33];
    int x = tid & 31, y = tid >> 5;   // 32 x 8
    int k0 = kt * 32, n0 = nt * 32;
    #pragma unroll
    for (int i = 0; i < 32; i += 8)
        t[y + i][x] = W[(size_t)(k0 + y + i) * N + n0 + x];
    __syncthreads();
    #pragma unroll
    for (int i = 0; i < 32; i += 8)
        WT[(size_t)(n0 + y + i) * K + k0 + x] = __float2half_rn(t[x][y + i]);
}

__global__ void __launch_bounds__(256) k_prep(
    const float* __restrict__ state,
    const float* __restrict__ W1, const float* __restrict__ W2,
    const float* __restrict__ Wf, const float* __restrict__ Wg,
    const float* __restrict__ bg, const float* __restrict__ bf)
{
    const int id = blockIdx.x, tid = threadIdx.x;
    if (id < 2048) {
        tr_tile(Wg, g_WgT, K_CAT, N_G, id & 63, id >> 6, tid);
    } else if (id < 2176) {
        int t = id - 2048;
        tr_tile(Wf, g_WfT, K_CAT, N_F, t & 63, t >> 6, tid);
    } else if (id < 2304) {
        int t = id - 2176;
        int e = t >> 4; t &= 15;
        tr_tile(W1 + (size_t)e * S_DIM * H_DIM,
                g_W1T + (size_t)e * S_DIM * H_DIM,
                S_DIM, H_DIM, t & 1, t >> 1, tid);
    } else if (id < 2816) {
        int t = id - 2304;
        int e = t >> 6; t &= 63;
        tr_tile(W2 + (size_t)e * H_DIM * H_DIM,
                g_W2T + (size_t)e * H_DIM * H_DIM,
                H_DIM, H_DIM, t & 7, t >> 3, tid);
    } else if (id < 3840) {
        size_t i = ((size_t)(id - 2816) * 256 + tid) * 4;
        float4 v = *(const float4*)(state + i);
        __half2 h0 = __floats2half2_rn(v.x, v.y);
        __half2 h1 = __floats2half2_rn(v.z, v.w);
        *(uint2*)(g_Sh + i) = make_uint2(*(uint32_t*)&h0, *(uint32_t*)&h1);
    } else {
        int q = (id - 3840) * 256 + tid;
        if (q < N_G) {
            float s = 0.f;
            #pragma unroll
            for (int e = 0; e < E_DIM; ++e) s += bg[(size_t)e * N_G + q];
            g_bsum[q] = s;
        } else if (q < N_G + N_F) {
            int qq = q - N_G;
            float s = 0.f;
            #pragma unroll
            for (int e = 0; e < E_DIM; ++e) s += bf[(size_t)e * N_F + qq];
            g_bsum[q] = s;
        }
    }
}

// ---------------------------------------------------------------------------
// Pass 1: CTA = (64 batch rows, member e). 128 threads / 4 warps,
// warp tile 64x64 (4 m-tiles x 8 n8-tiles). 2 CTAs/SM.
// SMEM: phase1 sS[64][72] + sW1[256][72]; phase2 sH[64][264] (aliases);
// W2 streamed in 8 chunks of K=32, stride 40, double-buffered after them.
// ---------------------------------------------------------------------------
__global__ void __launch_bounds__(128, 2) k_mlp(
    const float* __restrict__ b1, const float* __restrict__ b2)
{
    extern __shared__ __half smh[];
    __half* sS   = smh;                  // [64][72] phase 1
    __half* sW1  = smh + 64 * 72;        // [256][72] phase 1
    __half* sH   = smh;                  // [64][264] phase 2 (aliases sS/sW1)
    __half* sW2a = smh + 23040;          // [256][40]
    __half* sW2b = sW2a + 256 * 40;      // [256][40]

    const int tid = threadIdx.x;
    const int lane = tid & 31, wn = tid >> 5;        // 4 warps: wn 0..3
    const int g = lane >> 2, tg = lane & 3;
    const int mi = lane >> 3, ri = lane & 7;
    const int b0 = blockIdx.x * 64;
    const int e  = blockIdx.y;

    const __half* W1e = g_W1T + (size_t)e * H_DIM * S_DIM;
    const __half* W2e = g_W2T + (size_t)e * H_DIM * H_DIM;

    auto loadW2 = [&](__half* buf, int kc) {   // 256 rows x 32 halves
        #pragma unroll
        for (int j = 0; j < 8; ++j) {
            int lin = j * 128 + tid, row = lin >> 2, seg = lin & 3;
            cp16(buf + row * 40 + seg * 8, W2e + (size_t)row * 256 + kc * 32 + seg * 8);
        }
    };

    // phase-1 loads: state 64x64 halves, W1T 256x64
    #pragma unroll
    for (int j = 0; j < 4; ++j) {
        int lin = j * 128 + tid, row = lin >> 3, seg = lin & 7;
        cp16(sS + row * 72 + seg * 8, g_Sh + (size_t)(b0 + row) * S_DIM + seg * 8);
    }
    #pragma unroll
    for (int j = 0; j < 16; ++j) {
        int lin = j * 128 + tid, row = lin >> 3, seg = lin & 7;
        cp16(sW1 + row * 72 + seg * 8, W1e + (size_t)row * S_DIM + seg * 8);
    }
    cp_commit();
    loadW2(sW2a, 0); cp_commit();
    loadW2(sW2b, 1); cp_commit();
    cp_wait<2>(); __syncthreads();

    // fragment base offsets (bytes)
    const uint32_t uS = s2u(sS), uW1 = s2u(sW1);
    const uint32_t uH = s2u(sH), uW2 = s2u(sW2a);
    uint32_t aoff72[4], aoff264[4], boff72[4], boff40[4];
    #pragma unroll
    for (int t = 0; t < 4; ++t) {
        int rrow = t * 16 + ri + (mi & 1) * 8;
        int kadd = (mi >> 1) * 8;
        aoff72[t]  = (uint32_t)(rrow * 72  + kadd) * 2;
        aoff264[t] = (uint32_t)(rrow * 264 + kadd) * 2;
    }
    #pragma unroll
    for (int j = 0; j < 4; ++j) {
        int nrow = wn * 64 + (j * 2 + (lane >> 4)) * 8 + ri;
        int kadd = ((lane >> 3) & 1) * 8;
        boff72[j] = (uint32_t)(nrow * 72 + kadd) * 2;
        boff40[j] = (uint32_t)(nrow * 40 + kadd) * 2;
    }

    // ---- layer 1: K=64, 4 ksteps ----
    float acc[4][8][4];
    #pragma unroll
    for (int t = 0; t < 4; ++t)
        #pragma unroll
        for (int u = 0; u < 8; ++u)
            #pragma unroll
            for (int v = 0; v < 4; ++v) acc[t][u][v] = 0.f;

    #pragma unroll
    for (int ks = 0; ks < 4; ++ks) {
        uint32_t a[4][4], b[8][2];
        #pragma unroll
        for (int t = 0; t < 4; ++t) ldsm4(a[t], uS + aoff72[t] + ks * 32);
        #pragma unroll
        for (int j = 0; j < 4; ++j) {
            uint32_t r[4];
            ldsm4(r, uW1 + boff72[j] + ks * 32);
            b[2*j][0] = r[0]; b[2*j][1] = r[1];
            b[2*j+1][0] = r[2]; b[2*j+1][1] = r[3];
        }
        #pragma unroll
        for (int t = 0; t < 4; ++t)
            #pragma unroll
            for (int u = 0; u < 8; ++u)
                mma_f16(acc[t][u], a[t], b[u]);
    }
    __syncthreads();   // done reading sS / sW1

    // epilogue 1: tanh + bias -> sH
    #pragma unroll
    for (int t = 0; t < 4; ++t) {
        int r = t * 16 + g;
        #pragma unroll
        for (int u = 0; u < 8; ++u) {
            int cl = wn * 64 + u * 8 + tg * 2;
            float bb0 = b1[(size_t)e * H_DIM + cl];
            float bb1 = b1[(size_t)e * H_DIM + cl + 1];
            __half2 v0 = __floats2half2_rn(tanhf(acc[t][u][0] + bb0),
                                           tanhf(acc[t][u][1] + bb1));
            __half2 v1 = __floats2half2_rn(tanhf(acc[t][u][2] + bb0),
                                           tanhf(acc[t][u][3] + bb1));
            *(__half2*)(sH + r * 264 + cl)       = v0;
            *(__half2*)(sH + (r + 8) * 264 + cl) = v1;
        }
    }
    __syncthreads();

    // ---- layer 2: K=256, 8 chunks of 32 (2 ksteps each) ----
    #pragma unroll
    for (int t = 0; t < 4; ++t)
        #pragma unroll
        for (int u = 0; u < 8; ++u)
            #pragma unroll
            for (int v = 0; v < 4; ++v) acc[t][u][v] = 0.f;

    for (int kc = 0; kc < 8; ++kc) {
        if (kc < 7) cp_wait<1>(); else cp_wait<0>();
        __syncthreads();
        const uint32_t stB = uW2 + (uint32_t)(kc & 1) * (256 * 40 * 2);
        #pragma unroll
        for (int ks = 0; ks < 2; ++ks) {
            const uint32_t kbyteA = (uint32_t)(kc * 32 + ks * 16) * 2;
            uint32_t a[4][4], b[8][2];
            #pragma unroll
            for (int t = 0; t < 4; ++t) ldsm4(a[t], uH + aoff264[t] + kbyteA);
            #pragma unroll
            for (int j = 0; j < 4; ++j) {
                uint32_t r[4];
                ldsm4(r, stB + boff40[j] + ks * 32);
                b[2*j][0] = r[0]; b[2*j][1] = r[1];
                b[2*j+1][0] = r[2]; b[2*j+1][1] = r[3];
            }
            #pragma unroll
            for (int t = 0; t < 4; ++t)
                #pragma unroll
                for (int u = 0; u < 8; ++u)
                    mma_f16(acc[t][u], a[t], b[u]);
        }
        __syncthreads();
        if (kc + 2 < 8) {
            loadW2((kc & 1) ? sW2b : sW2a, kc + 2);
            cp_commit();
        }
    }

    // epilogue 2: tanh + bias -> g_H
    #pragma unroll
    for (int t = 0; t < 4; ++t) {
        size_t r = (size_t)b0 + t * 16 + g;
        #pragma unroll
        for (int u = 0; u < 8; ++u) {
            int cl = wn * 64 + u * 8 + tg * 2;
            float bb0 = b2[(size_t)e * H_DIM + cl];
            float bb1 = b2[(size_t)e * H_DIM + cl + 1];
            __half2 v0 = __floats2half2_rn(tanhf(acc[t][u][0] + bb0),
                                           tanhf(acc[t][u][1] + bb1));
            __half2 v1 = __floats2half2_rn(tanhf(acc[t][u][2] + bb0),
                                           tanhf(acc[t][u][3] + bb1));
            __half* dst = g_H + r * K_CAT + e * H_DIM + cl;
            *(__half2*)dst = v0;
            *(__half2*)(dst + 8 * K_CAT) = v1;
        }
    }
}

// ---------------------------------------------------------------------------
// Pass 2 tile worker (unchanged from round 7)
// ---------------------------------------------------------------------------
template<int NT>
__device__ __forceinline__ void gemm_tile(
    const __half* __restrict__ Abase, const __half* __restrict__ Bbase,
    const float* __restrict__ bsumN, float* __restrict__ outBase, int Ntot,
    __half* smh, int tid)
{
    constexpr int TN  = NT * 16;
    constexpr int NCH = K_CAT / 64;

    __half* sA = smh;
    __half* sB = smh + 3 * 128 * 72;
    float*  sBias = (float*)(sB + 3 * TN * 72);

    const int lane = tid & 31, w = tid >> 5;
    const int wm = w >> 1, wn = w & 1;
    const int g = lane >> 2, tg = lane & 3;
    const int mi = lane >> 3, ri = lane & 7;

    if (tid < TN) sBias[tid] = bsumN[tid];

    auto loadA = [&](int stage, int kc) {
        __half* buf = sA + stage * (128 * 72);
        #pragma unroll
        for (int j = 0; j < 8; ++j) {
            int lin = j * 128 + tid, row = lin >> 3, seg = lin & 7;
            cp16(buf + row * 72 + seg * 8, Abase + (size_t)row * K_CAT + kc * 64 + seg * 8);
        }
    };
    auto loadB = [&](int stage, int kc) {
        __half* buf = sB + stage * (TN * 72);
        #pragma unroll
        for (int j = 0; j < TN / 16; ++j) {
            int lin = j * 128 + tid, row = lin >> 3, seg = lin & 7;
            cp16(buf + row * 72 + seg * 8, Bbase + (size_t)row * K_CAT + kc * 64 + seg * 8);
        }
    };

    const uint32_t uA = s2u(sA), uB = s2u(sB);
    uint32_t aoff[4], boff[NT / 2];
    #pragma unroll
    for (int t = 0; t < 4; ++t)
        aoff[t] = (uint32_t)((wm * 64 + t * 16 + ri + (mi & 1) * 8) * 72 +
                             (mi >> 1) * 8) * 2;
    #pragma unroll
    for (int j = 0; j < NT / 2; ++j)
        boff[j] = (uint32_t)((wn * (TN / 2) + (j * 2 + (lane >> 4)) * 8 + ri) * 72 +
                             ((lane >> 3) & 1) * 8) * 2;

    float acc[4][NT][4];
    #pragma unroll
    for (int t = 0; t < 4; ++t)
        #pragma unroll
        for (int u = 0; u < NT; ++u)
            #pragma unroll
            for (int v = 0; v < 4; ++v) acc[t][u][v] = 0.f;

    loadA(0, 0); loadB(0, 0); cp_commit();
    loadA(1, 1); loadB(1, 1); cp_commit();

    for (int kc = 0; kc < NCH; ++kc) {
        if (kc + 1 < NCH) cp_wait<1>(); else cp_wait<0>();
        __syncthreads();
        if (kc + 2 < NCH) {
            loadA((kc + 2) % 3, kc + 2);
            loadB((kc + 2) % 3, kc + 2);
            cp_commit();
        }
        const int stage = kc % 3;
        const uint32_t stA = uA + (uint32_t)stage * (128 * 72 * 2);
        const uint32_t stB = uB + (uint32_t)stage * (TN * 72 * 2);

        #pragma unroll
        for (int ks = 0; ks < 4; ++ks) {
            uint32_t a[4][4], b[NT][2];
            #pragma unroll
            for (int t = 0; t < 4; ++t) ldsm4(a[t], stA + aoff[t] + ks * 32);
            #pragma unroll
            for (int j = 0; j < NT / 2; ++j) {
                uint32_t r[4];
                ldsm4(r, stB + boff[j] + ks * 32);
                b[2*j][0] = r[0]; b[2*j][1] = r[1];
                b[2*j+1][0] = r[2]; b[2*j+1][1] = r[3];
            }
            #pragma unroll
            for (int t = 0; t < 4; ++t)
                #pragma unroll
                for (int u = 0; u < NT; ++u)
                    mma_f16(acc[t][u], a[t], b[u]);
        }
    }

    #pragma unroll
    for (int t = 0; t < 4; ++t) {
        size_t r0 = wm * 64 + t * 16 + g;
        #pragma unroll
        for (int u = 0; u < NT; ++u) {
            int cl = wn * (TN / 2) + u * 8 + tg * 2;
            float bs0 = sBias[cl], bs1 = sBias[cl + 1];
            float2 v0, v1;
            v0.x = 0.125f * (acc[t][u][0] + bs0);
            v0.y = 0.125f * (acc[t][u][1] + bs1);
            v1.x = 0.125f * (acc[t][u][2] + bs0);
            v1.y = 0.125f * (acc[t][u][3] + bs1);
            *(float2*)(outBase + r0 * Ntot + cl)       = v0;
            *(float2*)(outBase + (r0 + 8) * Ntot + cl) = v1;
        }
    }
}

__global__ void __launch_bounds__(128, 2) k_out(
    float* __restrict__ out_f, float* __restrict__ out_g)
{
    extern __shared__ __half smh[];
    const int id = blockIdx.x, tid = threadIdx.x;
    if (id < 1024) {
        const int bm = id & 127, bn = id >> 7;
        gemm_tile<8>(g_H + (size_t)bm * 128 * K_CAT,
                     g_WgT + (size_t)bn * 128 * K_CAT,
                     g_bsum + bn * 128,
                     out_g + (size_t)bm * 128 * N_G + bn * 128,
                     N_G, smh, tid);
    } else {
        const int bm = id - 1024;
        gemm_tile<4>(g_H + (size_t)bm * 128 * K_CAT,
                     g_WfT,
                     g_bsum + N_G,
                     out_f + (size_t)bm * 128 * N_F,
                     N_F, smh, tid);
    }
}

// ---------------------------------------------------------------------------
extern "C" void kernel_launch(void* const* d_in, const int* in_sizes, int n_in,
                              void* d_out, int out_size)
{
    const float* state = (const float*)d_in[0];
    const float* W1    = (const float*)d_in[1];
    const float* b1    = (const float*)d_in[2];
    const float* W2    = (const float*)d_in[3];
    const float* b2    = (const float*)d_in[4];
    const float* Wf    = (const float*)d_in[5];
    const float* bf    = (const float*)d_in[6];
    const float* Wg    = (const float*)d_in[7];
    const float* bg    = (const float*)d_in[8];

    float* out   = (float*)d_out;
    float* out_f = out;                              // f_mean [B, 64]
    float* out_g = out + (size_t)B_DIM * S_DIM;      // g_mean [B, 1024]

    const int smemM = 23040 * 2 + 2 * 256 * 40 * 2;            // 87,040 B
    const int smemO = (3 * 128 * 72 + 3 * 128 * 72) * 2 + 512; // 111,104 B

    cudaFuncSetAttribute(k_mlp, cudaFuncAttributeMaxDynamicSharedMemorySize, smemM);
    cudaFuncSetAttribute(k_out, cudaFuncAttributeMaxDynamicSharedMemorySize, smemO);

    k_prep<<<3845, 256>>>(state, W1, W2, Wf, Wg, bg, bf);
    k_mlp<<<dim3(B_DIM / 64, E_DIM), 128, smemM>>>(b1, b2);
    k_out<<<1152, 128, smemO>>>(out_f, out_g);
}